// round 1
// baseline (speedup 1.0000x reference)
#include <cuda_runtime.h>
#include <math.h>
#include <float.h>

#define BHN  32      // B*H
#define LSEQ 2048
#define DIM  128
#define BLK  64
#define NB   32      // nQ = nK
#define TOP  4
#define GK   256     // TOP*BLK gathered keys
#define NCH  16      // split-K chunks for kvsum
#define CHL  (LSEQ/NCH)

// ---- scratch (static device globals; no runtime allocation) ----
__device__ float g_qb[BHN*NB*DIM];
__device__ float g_kb[BHN*NB*DIM];
__device__ int   g_lut[BHN*NB*TOP];
__device__ float g_phik[(size_t)BHN*LSEQ*DIM];                 // 33.5 MB
__device__ float g_kv[BHN*DIM*DIM];
__device__ float g_ksum[BHN*DIM];
__device__ float g_kv_part[(size_t)NCH*BHN*DIM*DIM];           // 33.5 MB
__device__ float g_ksum_part[NCH*BHN*DIM];

// ============================================================
// K1: block means of q and k  -> g_qb, g_kb
// grid = BHN*NB blocks, 128 threads
// ============================================================
__global__ void k_blockmean(const float* __restrict__ q, const float* __restrict__ k) {
    int blk = blockIdx.x;               // bh*NB + nb
    int d   = threadIdx.x;
    int bh  = blk >> 5, nb = blk & 31;
    size_t base = ((size_t)bh*LSEQ + (size_t)nb*BLK)*DIM + d;
    float sq = 0.f, sk = 0.f;
#pragma unroll 8
    for (int i = 0; i < BLK; i++) {
        sq += q[base + (size_t)i*DIM];
        sk += k[base + (size_t)i*DIM];
    }
    g_qb[blk*DIM + d] = sq * (1.f/BLK);
    g_kb[blk*DIM + d] = sk * (1.f/BLK);
}

// ============================================================
// K2: blk_scores = qb@kb^T and top-4 per q-row -> g_lut
// grid = BHN blocks, 1024 threads
// ============================================================
__global__ void k_topk() {
    __shared__ float sQ[NB][DIM];
    __shared__ float sK[NB][DIM+1];     // pad: row reads per-lane conflict-free
    __shared__ float sS[NB][NB];
    int bh  = blockIdx.x;
    int tid = threadIdx.x;

    for (int i = tid; i < NB*DIM; i += 1024) {
        sQ[i>>7][i&127] = g_qb[bh*NB*DIM + i];
        sK[i>>7][i&127] = g_kb[bh*NB*DIM + i];
    }
    __syncthreads();

    {
        int qr = tid >> 5, kr = tid & 31;
        float acc = 0.f;
#pragma unroll 8
        for (int kk = 0; kk < DIM; kk++) acc += sQ[qr][kk] * sK[kr][kk];
        sS[qr][kr] = acc;
    }
    __syncthreads();

    int qr = tid >> 5, lane = tid & 31;
    float v  = sS[qr][lane];
    int   mi = lane;
#pragma unroll
    for (int t = 0; t < TOP; t++) {
        float bv = v; int bi = mi;
#pragma unroll
        for (int off = 16; off; off >>= 1) {
            float ov = __shfl_xor_sync(0xffffffffu, bv, off);
            int   oi = __shfl_xor_sync(0xffffffffu, bi, off);
            if (ov > bv || (ov == bv && oi < bi)) { bv = ov; bi = oi; }
        }
        if (lane == 0) g_lut[(bh*NB + qr)*TOP + t] = bi;
        if (mi == bi) v = -FLT_MAX;     // remove winner, lowest-index tie-break
    }
}

// ============================================================
// K_phi: phi_k = softmax(k, axis=-1) -> g_phik
// warp per row; grid = BHN*LSEQ/8, 256 threads
// ============================================================
__global__ void k_phi(const float* __restrict__ k) {
    int row  = blockIdx.x*8 + (threadIdx.x >> 5);
    int lane = threadIdx.x & 31;
    const float* src = k + (size_t)row*DIM;
    float x0 = src[lane], x1 = src[lane+32], x2 = src[lane+64], x3 = src[lane+96];
    float m = fmaxf(fmaxf(x0,x1), fmaxf(x2,x3));
#pragma unroll
    for (int o = 16; o; o >>= 1) m = fmaxf(m, __shfl_xor_sync(0xffffffffu, m, o));
    float e0 = __expf(x0-m), e1 = __expf(x1-m), e2 = __expf(x2-m), e3 = __expf(x3-m);
    float s = e0+e1+e2+e3;
#pragma unroll
    for (int o = 16; o; o >>= 1) s += __shfl_xor_sync(0xffffffffu, s, o);
    float inv = 1.f/s;
    float* dst = g_phik + (size_t)row*DIM;
    dst[lane]=e0*inv; dst[lane+32]=e1*inv; dst[lane+64]=e2*inv; dst[lane+96]=e3*inv;
}

// ============================================================
// K_kv: split-K partials of kvsum = phi_k^T @ v and ksum
// grid = NCH*BHN, 256 threads, 8x8 register tile
// ============================================================
__global__ void __launch_bounds__(256) k_kvsum(const float* __restrict__ v) {
    __shared__ float sPhi[32][DIM];
    __shared__ float sV[32][DIM];
    int bid = blockIdx.x;
    int ch  = bid / BHN, bh = bid % BHN;
    int tid = threadIdx.x;
    int tr  = tid >> 4, tc = tid & 15;
    int d0  = tr*8, e0 = tc*8;

    float acc[8][8];
#pragma unroll
    for (int i = 0; i < 8; i++)
#pragma unroll
        for (int j = 0; j < 8; j++) acc[i][j] = 0.f;
    float ks[8] = {0,0,0,0,0,0,0,0};

    size_t lbase = (size_t)bh*LSEQ + (size_t)ch*CHL;
    for (int s = 0; s < CHL; s += 32) {
        for (int idx = tid; idx < 32*DIM; idx += 256) {
            int jl = idx >> 7, d = idx & 127;
            sPhi[jl][d] = g_phik[(lbase + s + jl)*DIM + d];
            sV[jl][d]   = v[(lbase + s + jl)*DIM + d];
        }
        __syncthreads();
#pragma unroll 4
        for (int jl = 0; jl < 32; jl++) {
            float4 a0 = *(const float4*)&sPhi[jl][d0];
            float4 a1 = *(const float4*)&sPhi[jl][d0+4];
            float4 b0 = *(const float4*)&sV[jl][e0];
            float4 b1 = *(const float4*)&sV[jl][e0+4];
            float a[8] = {a0.x,a0.y,a0.z,a0.w,a1.x,a1.y,a1.z,a1.w};
            float b[8] = {b0.x,b0.y,b0.z,b0.w,b1.x,b1.y,b1.z,b1.w};
#pragma unroll
            for (int i = 0; i < 8; i++)
#pragma unroll
                for (int j = 0; j < 8; j++) acc[i][j] += a[i]*b[j];
            if (tc == 0) {
#pragma unroll
                for (int i = 0; i < 8; i++) ks[i] += a[i];
            }
        }
        __syncthreads();
    }
    float* dst = g_kv_part + (size_t)bid*DIM*DIM;
#pragma unroll
    for (int i = 0; i < 8; i++) {
        float4 o0 = make_float4(acc[i][0],acc[i][1],acc[i][2],acc[i][3]);
        float4 o1 = make_float4(acc[i][4],acc[i][5],acc[i][6],acc[i][7]);
        *(float4*)&dst[(d0+i)*DIM + e0]     = o0;
        *(float4*)&dst[(d0+i)*DIM + e0 + 4] = o1;
    }
    if (tc == 0) {
#pragma unroll
        for (int i = 0; i < 8; i++) g_ksum_part[bid*DIM + d0 + i] = ks[i];
    }
}

// ============================================================
// K_red: deterministic reduction of split-K partials
// ============================================================
__global__ void k_reduce() {
    int idx = blockIdx.x*256 + threadIdx.x;     // BHN*DIM*DIM total
    float s = 0.f;
#pragma unroll
    for (int ch = 0; ch < NCH; ch++) s += g_kv_part[(size_t)ch*BHN*DIM*DIM + idx];
    g_kv[idx] = s;
    if (idx < BHN*DIM) {
        float t = 0.f;
#pragma unroll
        for (int ch = 0; ch < NCH; ch++) t += g_ksum_part[ch*BHN*DIM + idx];
        g_ksum[idx] = t;
    }
}

// ============================================================
// K3: sparse attention. grid = BHN*NB, 256 threads, dyn smem.
// Q^T[128][64] (stride 68), K^T[128][128] (stride 132, reused as V[64][128]),
// S[64][257]
// ============================================================
#define QS 68
#define KS 132
#define SS 257

__global__ void __launch_bounds__(256) k_sparse(const float* __restrict__ q,
                                                const float* __restrict__ k,
                                                const float* __restrict__ v,
                                                float* __restrict__ out) {
    extern __shared__ float sm[];
    float* sQt  = sm;                    // DIM*QS
    float* sKt  = sQt + DIM*QS;          // DIM*KS (also V tile [64][128])
    float* sS   = sKt + DIM*KS;          // 64*SS
    float* srow = sS + 64*SS;            // 64 inverse row sums
    __shared__ int slut[TOP];

    int bid = blockIdx.x;
    int bh  = bid >> 5, qb = bid & 31;
    int tid = threadIdx.x;
    if (tid < TOP) slut[tid] = g_lut[bid*TOP + tid];

    size_t qbase = ((size_t)bh*LSEQ + (size_t)qb*BLK)*DIM;
    for (int idx = tid; idx < BLK*DIM; idx += 256) {
        int r = idx >> 7, d = idx & 127;
        sQt[d*QS + r] = q[qbase + (size_t)r*DIM + d];
    }
    __syncthreads();

    const float scale = 0.08838834764831845f;   // 1/sqrt(128)
    int tr = tid >> 4, tc = tid & 15;

    // ---- scores: two 128-key chunks ----
    for (int ch = 0; ch < 2; ch++) {
        for (int idx = tid; idx < 128*DIM; idx += 256) {
            int j = idx >> 7, d = idx & 127;
            int t = ch*2 + (j >> 6);
            int blkid = slut[t];
            sKt[d*KS + j] = k[((size_t)bh*LSEQ + (size_t)blkid*BLK + (j & 63))*DIM + d];
        }
        __syncthreads();
        float acc[4][8];
#pragma unroll
        for (int i = 0; i < 4; i++)
#pragma unroll
            for (int j = 0; j < 8; j++) acc[i][j] = 0.f;
#pragma unroll 2
        for (int kk = 0; kk < DIM; kk++) {
            float4 qf = *(const float4*)&sQt[kk*QS + tr*4];
            float4 k0 = *(const float4*)&sKt[kk*KS + tc*8];
            float4 k1 = *(const float4*)&sKt[kk*KS + tc*8 + 4];
            float a[4] = {qf.x,qf.y,qf.z,qf.w};
            float b[8] = {k0.x,k0.y,k0.z,k0.w,k1.x,k1.y,k1.z,k1.w};
#pragma unroll
            for (int i = 0; i < 4; i++)
#pragma unroll
                for (int j = 0; j < 8; j++) acc[i][j] += a[i]*b[j];
        }
#pragma unroll
        for (int i = 0; i < 4; i++) {
            int row = tr*4 + i;
#pragma unroll
            for (int j = 0; j < 8; j++)
                sS[row*SS + ch*128 + tc*8 + j] = acc[i][j]*scale;
        }
        __syncthreads();
    }

    // ---- softmax (keep unnormalized exp; scale at epilogue) ----
    if (tid < BLK) {
        float* rp = sS + tid*SS;
        float m = -FLT_MAX;
#pragma unroll 8
        for (int j = 0; j < GK; j++) m = fmaxf(m, rp[j]);
        float s = 0.f;
#pragma unroll 4
        for (int j = 0; j < GK; j++) { float e = __expf(rp[j]-m); rp[j] = e; s += e; }
        srow[tid] = 1.f/s;
    }
    __syncthreads();

    // ---- PV ----
    float oac[4][8];
#pragma unroll
    for (int i = 0; i < 4; i++)
#pragma unroll
        for (int j = 0; j < 8; j++) oac[i][j] = 0.f;

    for (int t = 0; t < TOP; t++) {
        int blkid = slut[t];
        for (int idx = tid; idx < BLK*DIM; idx += 256) {
            int j = idx >> 7, d = idx & 127;
            sKt[j*DIM + d] = v[((size_t)bh*LSEQ + (size_t)blkid*BLK + j)*DIM + d];
        }
        __syncthreads();
#pragma unroll 2
        for (int jl = 0; jl < BLK; jl++) {
            int jg = t*BLK + jl;
            float p[4];
#pragma unroll
            for (int i = 0; i < 4; i++) p[i] = sS[(tr*4+i)*SS + jg];
            float4 v0 = *(const float4*)&sKt[jl*DIM + tc*8];
            float4 v1 = *(const float4*)&sKt[jl*DIM + tc*8 + 4];
            float b[8] = {v0.x,v0.y,v0.z,v0.w,v1.x,v1.y,v1.z,v1.w};
#pragma unroll
            for (int i = 0; i < 4; i++)
#pragma unroll
                for (int j = 0; j < 8; j++) oac[i][j] += p[i]*b[j];
        }
        __syncthreads();
    }

#pragma unroll
    for (int i = 0; i < 4; i++) {
        int row = tr*4 + i;
        float inv = srow[row];
        float* op = out + qbase + (size_t)row*DIM + tc*8;
        float4 o0 = make_float4(oac[i][0]*inv, oac[i][1]*inv, oac[i][2]*inv, oac[i][3]*inv);
        float4 o1 = make_float4(oac[i][4]*inv, oac[i][5]*inv, oac[i][6]*inv, oac[i][7]*inv);
        *(float4*)op       = o0;
        *(float4*)(op + 4) = o1;
    }
}

// ============================================================
// K5: linear half + projection; out += o_l
// grid = BHN*NB, 256 threads, dyn smem.
// ============================================================
#define WS 132
#define PS 132

__global__ void __launch_bounds__(256) k_linear(const float* __restrict__ q,
                                                const float* __restrict__ w,
                                                const float* __restrict__ bpr,
                                                float* __restrict__ out) {
    extern __shared__ float sm[];
    float* sKV  = sm;                    // DIM*DIM, kvsum natural [d][e]
    float* sWt  = sKV + DIM*DIM;         // DIM*WS, W transposed [e][e2]
    float* sP   = sWt + DIM*WS;          // BLK*PS, phi_q then o_pre
    float* sden = sP + BLK*PS;           // BLK
    float* sks  = sden + BLK;            // DIM

    int bid = blockIdx.x;
    int bh  = bid >> 5, qb = bid & 31;
    int tid = threadIdx.x;

    for (int idx = tid; idx < DIM*DIM; idx += 256) sKV[idx] = g_kv[bh*DIM*DIM + idx];
    for (int idx = tid; idx < DIM*DIM; idx += 256) {
        int e2 = idx >> 7, e = idx & 127;
        sWt[e*WS + e2] = w[idx];
    }
    if (tid < DIM) sks[tid] = g_ksum[bh*DIM + tid];

    size_t qbase = ((size_t)bh*LSEQ + (size_t)qb*BLK)*DIM;
    int wid = tid >> 5, lane = tid & 31;
    for (int r = wid; r < BLK; r += 8) {
        const float* src = q + qbase + (size_t)r*DIM;
        float x0 = src[lane], x1 = src[lane+32], x2 = src[lane+64], x3 = src[lane+96];
        float m = fmaxf(fmaxf(x0,x1), fmaxf(x2,x3));
#pragma unroll
        for (int o = 16; o; o >>= 1) m = fmaxf(m, __shfl_xor_sync(0xffffffffu, m, o));
        float e0 = __expf(x0-m), e1 = __expf(x1-m), e2 = __expf(x2-m), e3 = __expf(x3-m);
        float s = e0+e1+e2+e3;
#pragma unroll
        for (int o = 16; o; o >>= 1) s += __shfl_xor_sync(0xffffffffu, s, o);
        float inv = 1.f/s;
        float* dst = sP + r*PS;
        dst[lane]=e0*inv; dst[lane+32]=e1*inv; dst[lane+64]=e2*inv; dst[lane+96]=e3*inv;
    }
    __syncthreads();

    if (tid < BLK) {
        float s = 0.f;
#pragma unroll 8
        for (int d = 0; d < DIM; d++) s += sP[tid*PS + d] * sks[d];
        sden[tid] = 1.f/(1e-5f + s);
    }
    __syncthreads();

    int tr = tid >> 4, tc = tid & 15;

    // gemm1: num = phi_q @ kvsum
    float acc[4][8];
#pragma unroll
    for (int i = 0; i < 4; i++)
#pragma unroll
        for (int j = 0; j < 8; j++) acc[i][j] = 0.f;
#pragma unroll 2
    for (int dd = 0; dd < DIM; dd++) {
        float p[4];
#pragma unroll
        for (int i = 0; i < 4; i++) p[i] = sP[(tr*4+i)*PS + dd];
        float4 b0 = *(const float4*)&sKV[dd*DIM + tc*8];
        float4 b1 = *(const float4*)&sKV[dd*DIM + tc*8 + 4];
        float b[8] = {b0.x,b0.y,b0.z,b0.w,b1.x,b1.y,b1.z,b1.w};
#pragma unroll
        for (int i = 0; i < 4; i++)
#pragma unroll
            for (int j = 0; j < 8; j++) acc[i][j] += p[i]*b[j];
    }
    __syncthreads();

    // o_pre = num / (1e-5 + den), back into sP
#pragma unroll
    for (int i = 0; i < 4; i++) {
        int row = tr*4 + i;
        float dn = sden[row];
#pragma unroll
        for (int j = 0; j < 8; j++) sP[row*PS + tc*8 + j] = acc[i][j]*dn;
    }
    __syncthreads();

    // gemm2: o_l = o_pre @ W^T ; out += o_l + b
    float acc2[4][8];
#pragma unroll
    for (int i = 0; i < 4; i++)
#pragma unroll
        for (int j = 0; j < 8; j++) acc2[i][j] = 0.f;
#pragma unroll 2
    for (int e = 0; e < DIM; e++) {
        float p[4];
#pragma unroll
        for (int i = 0; i < 4; i++) p[i] = sP[(tr*4+i)*PS + e];
        float4 b0 = *(const float4*)&sWt[e*WS + tc*8];
        float4 b1 = *(const float4*)&sWt[e*WS + tc*8 + 4];
        float b[8] = {b0.x,b0.y,b0.z,b0.w,b1.x,b1.y,b1.z,b1.w};
#pragma unroll
        for (int i = 0; i < 4; i++)
#pragma unroll
            for (int j = 0; j < 8; j++) acc2[i][j] += p[i]*b[j];
    }

    float bb[8];
#pragma unroll
    for (int j = 0; j < 8; j++) bb[j] = bpr[tc*8 + j];
#pragma unroll
    for (int i = 0; i < 4; i++) {
        int row = tr*4 + i;
        float* op = out + qbase + (size_t)row*DIM + tc*8;
        float4 o0 = *(float4*)op;
        float4 o1 = *(float4*)(op + 4);
        o0.x += acc2[i][0] + bb[0]; o0.y += acc2[i][1] + bb[1];
        o0.z += acc2[i][2] + bb[2]; o0.w += acc2[i][3] + bb[3];
        o1.x += acc2[i][4] + bb[4]; o1.y += acc2[i][5] + bb[5];
        o1.z += acc2[i][6] + bb[6]; o1.w += acc2[i][7] + bb[7];
        *(float4*)op       = o0;
        *(float4*)(op + 4) = o1;
    }
}

// ============================================================
extern "C" void kernel_launch(void* const* d_in, const int* in_sizes, int n_in,
                              void* d_out, int out_size) {
    const float* q = (const float*)d_in[0];
    const float* k = (const float*)d_in[1];
    const float* v = (const float*)d_in[2];
    const float* w = (const float*)d_in[3];
    const float* b = (const float*)d_in[4];
    float* out = (float*)d_out;

    int sm3 = (DIM*QS + DIM*KS + 64*SS + 64) * (int)sizeof(float);
    int sm5 = (DIM*DIM + DIM*WS + BLK*PS + BLK + DIM) * (int)sizeof(float);
    cudaFuncSetAttribute(k_sparse, cudaFuncAttributeMaxDynamicSharedMemorySize, sm3);
    cudaFuncSetAttribute(k_linear, cudaFuncAttributeMaxDynamicSharedMemorySize, sm5);

    k_blockmean<<<BHN*NB, DIM>>>(q, k);
    k_topk<<<BHN, 1024>>>();
    k_phi<<<BHN*LSEQ/8, 256>>>(k);
    k_kvsum<<<NCH*BHN, 256>>>(v);
    k_reduce<<<(BHN*DIM*DIM)/256, 256>>>();
    k_sparse<<<BHN*NB, 256, sm3>>>(q, k, v, out);
    k_linear<<<BHN*NB, 256, sm5>>>(q, w, b, out);
}

// round 2
// speedup vs baseline: 1.8021x; 1.8021x over previous
#include <cuda_runtime.h>
#include <math.h>
#include <float.h>
#include <stdint.h>

#define BHN  32      // B*H
#define LSEQ 2048
#define DIM  128
#define BLK  64
#define NB   32      // nQ = nK
#define TOP  4
#define GK   256     // TOP*BLK gathered keys
#define NCH  16      // split-K chunks for kvsum
#define CHL  (LSEQ/NCH)   // 128

// ---- scratch ----
__device__ float g_qb[BHN*NB*DIM];
__device__ float g_kb[BHN*NB*DIM];
__device__ int   g_lut[BHN*NB*TOP];
__device__ float g_kv[BHN*DIM*DIM];
__device__ float g_ksum[BHN*DIM];
__device__ float g_kv_part[(size_t)NCH*BHN*DIM*DIM];
__device__ float g_ksum_part[NCH*BHN*DIM];

// ---- tf32 mma helpers ----
__device__ __forceinline__ uint32_t f2t(float f) {
    uint32_t r; asm("cvt.rna.tf32.f32 %0, %1;" : "=r"(r) : "f"(f)); return r;
}
__device__ __forceinline__ void mma8(float* c,
        uint32_t a0, uint32_t a1, uint32_t a2, uint32_t a3,
        uint32_t b0, uint32_t b1) {
    asm volatile(
        "mma.sync.aligned.m16n8k8.row.col.f32.tf32.tf32.f32 "
        "{%0,%1,%2,%3},{%4,%5,%6,%7},{%8,%9},{%0,%1,%2,%3};\n"
        : "+f"(c[0]), "+f"(c[1]), "+f"(c[2]), "+f"(c[3])
        : "r"(a0), "r"(a1), "r"(a2), "r"(a3), "r"(b0), "r"(b1));
}

// ============================================================
// K1: block means of q and k (exact fp32 — feeds top-k selection)
// ============================================================
__global__ void k_blockmean(const float* __restrict__ q, const float* __restrict__ k) {
    int blk = blockIdx.x;
    int d   = threadIdx.x;
    int bh  = blk >> 5, nb = blk & 31;
    size_t base = ((size_t)bh*LSEQ + (size_t)nb*BLK)*DIM + d;
    float sq = 0.f, sk = 0.f;
#pragma unroll 8
    for (int i = 0; i < BLK; i++) {
        sq += q[base + (size_t)i*DIM];
        sk += k[base + (size_t)i*DIM];
    }
    g_qb[blk*DIM + d] = sq * (1.f/BLK);
    g_kb[blk*DIM + d] = sk * (1.f/BLK);
}

// ============================================================
// K2: blk_scores + top-4 (exact fp32, lowest-index tie-break)
// ============================================================
__global__ void k_topk() {
    __shared__ float sQ[NB][DIM];
    __shared__ float sK[NB][DIM+1];
    __shared__ float sS[NB][NB];
    int bh  = blockIdx.x;
    int tid = threadIdx.x;

    for (int i = tid; i < NB*DIM; i += 1024) {
        sQ[i>>7][i&127] = g_qb[bh*NB*DIM + i];
        sK[i>>7][i&127] = g_kb[bh*NB*DIM + i];
    }
    __syncthreads();
    {
        int qr = tid >> 5, kr = tid & 31;
        float acc = 0.f;
#pragma unroll 8
        for (int kk = 0; kk < DIM; kk++) acc += sQ[qr][kk] * sK[kr][kk];
        sS[qr][kr] = acc;
    }
    __syncthreads();

    int qr = tid >> 5, lane = tid & 31;
    float v  = sS[qr][lane];
    int   mi = lane;
#pragma unroll
    for (int t = 0; t < TOP; t++) {
        float bv = v; int bi = mi;
#pragma unroll
        for (int off = 16; off; off >>= 1) {
            float ov = __shfl_xor_sync(0xffffffffu, bv, off);
            int   oi = __shfl_xor_sync(0xffffffffu, bi, off);
            if (ov > bv || (ov == bv && oi < bi)) { bv = ov; bi = oi; }
        }
        if (lane == 0) g_lut[(bh*NB + qr)*TOP + t] = bi;
        if (mi == bi) v = -FLT_MAX;
    }
}

// ============================================================
// K_kvsum: fused phi_k softmax + split-K kvsum = phi_k^T @ v (tf32 mma)
// grid = NCH*BHN, 256 threads.  smem: sPhi[128][136], sV[128][136] (tf32 bits)
// ============================================================
#define PHS 136
__global__ void __launch_bounds__(256) k_kvsum(const float* __restrict__ kin,
                                               const float* __restrict__ v) {
    extern __shared__ uint32_t usm[];
    uint32_t* sPhi = usm;             // 128*PHS
    uint32_t* sV   = sPhi + 128*PHS;  // 128*PHS

    int bid = blockIdx.x;
    int ch  = bid >> 5, bh = bid & 31;
    int tid = threadIdx.x, lane = tid & 31, warp = tid >> 5;
    int g = lane >> 2, tig = lane & 3;
    size_t lbase = (size_t)bh*LSEQ + (size_t)ch*CHL;

    // phi_k rows (warp per row, 16 rows/warp)
    for (int i = 0; i < 16; i++) {
        int r = warp*16 + i;
        const float* src = kin + (lbase + r)*DIM;
        float x0 = src[lane], x1 = src[lane+32], x2 = src[lane+64], x3 = src[lane+96];
        float m = fmaxf(fmaxf(x0,x1), fmaxf(x2,x3));
#pragma unroll
        for (int o = 16; o; o >>= 1) m = fmaxf(m, __shfl_xor_sync(0xffffffffu, m, o));
        float e0 = __expf(x0-m), e1 = __expf(x1-m), e2 = __expf(x2-m), e3 = __expf(x3-m);
        float s = e0+e1+e2+e3;
#pragma unroll
        for (int o = 16; o; o >>= 1) s += __shfl_xor_sync(0xffffffffu, s, o);
        float inv = 1.f/s;
        uint32_t* dst = sPhi + r*PHS;
        dst[lane]    = f2t(e0*inv);
        dst[lane+32] = f2t(e1*inv);
        dst[lane+64] = f2t(e2*inv);
        dst[lane+96] = f2t(e3*inv);
    }
    // V tile
    for (int idx = tid; idx < CHL*DIM; idx += 256) {
        int r = idx >> 7, d = idx & 127;
        sV[r*PHS + d] = f2t(v[(lbase + r)*DIM + d]);
    }
    __syncthreads();

    // ksum partial (column sums of phi; tf32 bits are valid floats)
    if (tid < DIM) {
        float s = 0.f;
#pragma unroll 8
        for (int r = 0; r < CHL; r++) s += __uint_as_float(sPhi[r*PHS + tid]);
        g_ksum_part[bid*DIM + tid] = s;
    }

    // GEMM: out[d][e] += sum_l phi[l][d]*v[l][e];  M=128(d) N=128(e) K=128(l)
    // warp = m-tile (16 rows), 16 n-tiles per warp
    float acc[16][4];
#pragma unroll
    for (int i = 0; i < 16; i++)
#pragma unroll
        for (int j = 0; j < 4; j++) acc[i][j] = 0.f;

    int m0 = warp*16;
#pragma unroll
    for (int kk = 0; kk < 16; kk++) {
        int k0 = kk*8;
        uint32_t a0 = sPhi[(k0+tig)*PHS   + m0 + g];
        uint32_t a1 = sPhi[(k0+tig)*PHS   + m0 + 8 + g];
        uint32_t a2 = sPhi[(k0+4+tig)*PHS + m0 + g];
        uint32_t a3 = sPhi[(k0+4+tig)*PHS + m0 + 8 + g];
#pragma unroll
        for (int nt = 0; nt < 16; nt++) {
            int n0 = nt*8;
            uint32_t b0 = sV[(k0+tig)*PHS   + n0 + g];
            uint32_t b1 = sV[(k0+4+tig)*PHS + n0 + g];
            mma8(acc[nt], a0, a1, a2, a3, b0, b1);
        }
    }
    float* dst = g_kv_part + (size_t)bid*DIM*DIM;
#pragma unroll
    for (int nt = 0; nt < 16; nt++) {
        int col = nt*8 + 2*tig;
        int row = m0 + g;
        *(float2*)&dst[row*DIM + col]     = make_float2(acc[nt][0], acc[nt][1]);
        *(float2*)&dst[(row+8)*DIM + col] = make_float2(acc[nt][2], acc[nt][3]);
    }
}

// ============================================================
// K_red: deterministic split-K reduction
// ============================================================
__global__ void k_reduce() {
    int idx = blockIdx.x*256 + threadIdx.x;
    float s = 0.f;
#pragma unroll
    for (int ch = 0; ch < NCH; ch++) s += g_kv_part[(size_t)ch*BHN*DIM*DIM + idx];
    g_kv[idx] = s;
    if (idx < BHN*DIM) {
        float t = 0.f;
#pragma unroll
        for (int ch = 0; ch < NCH; ch++) t += g_ksum_part[ch*BHN*DIM + idx];
        g_ksum[idx] = t;
    }
}

// ============================================================
// K3: sparse attention with tf32 mma.
// grid = BHN*NB, 256 threads = 8 warps.
// ============================================================
#define QST 132
#define KTS 68
#define VTS 136
#define SST 260
#define KVBUF 8704   // max(128*KTS, 64*VTS) = 8704

__global__ void __launch_bounds__(256) k_sparse(const float* __restrict__ q,
                                                const float* __restrict__ k,
                                                const float* __restrict__ v,
                                                float* __restrict__ out) {
    extern __shared__ uint32_t usm[];
    uint32_t* sQ   = usm;                  // 64*QST
    uint32_t* sKt  = sQ + 64*QST;          // KVBUF (K^T tiles, then V tiles)
    uint32_t* sS   = sKt + KVBUF;          // 64*SST (fp32 scores -> tf32 exp)
    float*    sSf  = (float*)sS;
    float*    srow = (float*)(sS + 64*SST);
    __shared__ int slut[TOP];

    int bid = blockIdx.x, bh = bid >> 5, qb = bid & 31;
    int tid = threadIdx.x, lane = tid & 31, warp = tid >> 5;
    int g = lane >> 2, tig = lane & 3;
    int mt = warp & 3, ns = warp >> 2;   // 4 m-tiles x 2 n-subsets

    if (tid < TOP) slut[tid] = g_lut[bid*TOP + tid];

    size_t qbase = ((size_t)bh*LSEQ + (size_t)qb*BLK)*DIM;
    for (int idx = tid; idx < BLK*DIM; idx += 256) {
        int r = idx >> 7, d = idx & 127;
        sQ[r*QST + d] = f2t(q[qbase + (size_t)r*DIM + d]);
    }
    __syncthreads();

    const float scale = 0.08838834764831845f;

    // ---- scores: S = Q @ K^T per key block ----
    for (int t = 0; t < TOP; t++) {
        size_t kb = ((size_t)bh*LSEQ + (size_t)slut[t]*BLK)*DIM;
        for (int idx = tid; idx < BLK*DIM; idx += 256) {
            int j = idx >> 7, d = idx & 127;
            sKt[d*KTS + j] = f2t(k[kb + (size_t)j*DIM + d]);
        }
        __syncthreads();

        float acc[4][4];
#pragma unroll
        for (int i = 0; i < 4; i++)
#pragma unroll
            for (int j = 0; j < 4; j++) acc[i][j] = 0.f;

#pragma unroll
        for (int kk = 0; kk < 16; kk++) {
            int k0 = kk*8;
            const uint32_t* qa = sQ + (mt*16+g)*QST + k0 + tig;
            uint32_t a0 = qa[0], a1 = qa[8*QST], a2 = qa[4], a3 = qa[8*QST+4];
#pragma unroll
            for (int nt = 0; nt < 4; nt++) {
                int n0 = ns*32 + nt*8;
                uint32_t b0 = sKt[(k0+tig)*KTS   + n0 + g];
                uint32_t b1 = sKt[(k0+4+tig)*KTS + n0 + g];
                mma8(acc[nt], a0, a1, a2, a3, b0, b1);
            }
        }
#pragma unroll
        for (int nt = 0; nt < 4; nt++) {
            int col = t*64 + ns*32 + nt*8 + 2*tig;
            int row = mt*16 + g;
            *(float2*)&sSf[row*SST + col]     = make_float2(acc[nt][0]*scale, acc[nt][1]*scale);
            *(float2*)&sSf[(row+8)*SST + col] = make_float2(acc[nt][2]*scale, acc[nt][3]*scale);
        }
        __syncthreads();
    }

    // ---- softmax: 4 threads per row, bank-friendly interleave ----
    {
        int row = tid >> 2, sub = tid & 3;
        float* rp = sSf + row*SST;
        float m = -FLT_MAX;
#pragma unroll 8
        for (int jj = 0; jj < 64; jj++) m = fmaxf(m, rp[sub + jj*4]);
        m = fmaxf(m, __shfl_xor_sync(0xffffffffu, m, 1));
        m = fmaxf(m, __shfl_xor_sync(0xffffffffu, m, 2));
        float s = 0.f;
#pragma unroll 4
        for (int jj = 0; jj < 64; jj++) {
            int j = sub + jj*4;
            float e = __expf(rp[j] - m);
            s += e;
            sS[row*SST + j] = f2t(e);
        }
        s += __shfl_xor_sync(0xffffffffu, s, 1);
        s += __shfl_xor_sync(0xffffffffu, s, 2);
        if (sub == 0) srow[row] = 1.f/s;
    }
    __syncthreads();

    // ---- PV: O = P @ V ----
    uint32_t* sV = sKt;
    int nh = warp >> 2;   // 4 m-tiles x 2 d-halves
    float oac[8][4];
#pragma unroll
    for (int i = 0; i < 8; i++)
#pragma unroll
        for (int j = 0; j < 4; j++) oac[i][j] = 0.f;

    for (int t = 0; t < TOP; t++) {
        size_t vb = ((size_t)bh*LSEQ + (size_t)slut[t]*BLK)*DIM;
        for (int idx = tid; idx < BLK*DIM; idx += 256) {
            int jl = idx >> 7, d = idx & 127;
            sV[jl*VTS + d] = f2t(v[vb + (size_t)jl*DIM + d]);
        }
        __syncthreads();
#pragma unroll
        for (int kk = 0; kk < 8; kk++) {
            int kg = t*64 + kk*8;
            const uint32_t* pa = sS + (mt*16+g)*SST + kg + tig;
            uint32_t a0 = pa[0], a1 = pa[8*SST], a2 = pa[4], a3 = pa[8*SST+4];
#pragma unroll
            for (int nt = 0; nt < 8; nt++) {
                int n0 = nh*64 + nt*8;
                uint32_t b0 = sV[(kk*8+tig)*VTS   + n0 + g];
                uint32_t b1 = sV[(kk*8+4+tig)*VTS + n0 + g];
                mma8(oac[nt], a0, a1, a2, a3, b0, b1);
            }
        }
        __syncthreads();
    }

    float i0 = srow[mt*16 + g], i1 = srow[mt*16 + 8 + g];
#pragma unroll
    for (int nt = 0; nt < 8; nt++) {
        int col = nh*64 + nt*8 + 2*tig;
        float* op0 = out + qbase + (size_t)(mt*16+g)*DIM + col;
        float* op1 = out + qbase + (size_t)(mt*16+8+g)*DIM + col;
        *(float2*)op0 = make_float2(oac[nt][0]*i0, oac[nt][1]*i0);
        *(float2*)op1 = make_float2(oac[nt][2]*i1, oac[nt][3]*i1);
    }
}

// ============================================================
// K5: linear half (phi_q softmax fused) + projection, tf32 mma; out += o_l
// grid = BHN*NB, 256 threads
// ============================================================
#define KVS 136
#define WTS 137
#define PST 132

__global__ void __launch_bounds__(256) k_linear(const float* __restrict__ q,
                                                const float* __restrict__ w,
                                                const float* __restrict__ bpr,
                                                float* __restrict__ out) {
    extern __shared__ uint32_t usm[];
    uint32_t* sKV = usm;                    // 128*KVS
    uint32_t* sWt = sKV + DIM*KVS;          // 128*WTS
    uint32_t* sP  = sWt + DIM*WTS;          // 64*PST (phi_q, then o_pre, tf32)
    float* sden = (float*)(sP + 64*PST);    // 64
    float* sks  = sden + 64;                // 128

    int bid = blockIdx.x, bh = bid >> 5, qb = bid & 31;
    int tid = threadIdx.x, lane = tid & 31, warp = tid >> 5;
    int g = lane >> 2, tig = lane & 3;
    int mt = warp & 3, nh = warp >> 2;

    for (int idx = tid; idx < DIM*DIM; idx += 256) {
        int d = idx >> 7, e = idx & 127;
        sKV[d*KVS + e] = f2t(g_kv[bh*DIM*DIM + idx]);
    }
    for (int idx = tid; idx < DIM*DIM; idx += 256) {
        int e2 = idx >> 7, e = idx & 127;
        sWt[e*WTS + e2] = f2t(w[idx]);
    }
    if (tid < DIM) sks[tid] = g_ksum[bh*DIM + tid];
    __syncthreads();

    // phi_q softmax + den, warp per row
    size_t qbase = ((size_t)bh*LSEQ + (size_t)qb*BLK)*DIM;
    for (int r = warp; r < BLK; r += 8) {
        const float* src = q + qbase + (size_t)r*DIM;
        float x0 = src[lane], x1 = src[lane+32], x2 = src[lane+64], x3 = src[lane+96];
        float m = fmaxf(fmaxf(x0,x1), fmaxf(x2,x3));
#pragma unroll
        for (int o = 16; o; o >>= 1) m = fmaxf(m, __shfl_xor_sync(0xffffffffu, m, o));
        float e0 = __expf(x0-m), e1 = __expf(x1-m), e2 = __expf(x2-m), e3 = __expf(x3-m);
        float s = e0+e1+e2+e3;
#pragma unroll
        for (int o = 16; o; o >>= 1) s += __shfl_xor_sync(0xffffffffu, s, o);
        float inv = 1.f/s;
        e0 *= inv; e1 *= inv; e2 *= inv; e3 *= inv;
        float dp = e0*sks[lane] + e1*sks[lane+32] + e2*sks[lane+64] + e3*sks[lane+96];
#pragma unroll
        for (int o = 16; o; o >>= 1) dp += __shfl_xor_sync(0xffffffffu, dp, o);
        uint32_t* dst = sP + r*PST;
        dst[lane]    = f2t(e0);
        dst[lane+32] = f2t(e1);
        dst[lane+64] = f2t(e2);
        dst[lane+96] = f2t(e3);
        if (lane == 0) sden[r] = 1.f/(1e-5f + dp);
    }
    __syncthreads();

    // gemm1: num = phi_q @ kvsum
    float acc[8][4];
#pragma unroll
    for (int i = 0; i < 8; i++)
#pragma unroll
        for (int j = 0; j < 4; j++) acc[i][j] = 0.f;
#pragma unroll
    for (int kk = 0; kk < 16; kk++) {
        int k0 = kk*8;
        const uint32_t* pa = sP + (mt*16+g)*PST + k0 + tig;
        uint32_t a0 = pa[0], a1 = pa[8*PST], a2 = pa[4], a3 = pa[8*PST+4];
#pragma unroll
        for (int nt = 0; nt < 8; nt++) {
            int n0 = nh*64 + nt*8;
            uint32_t b0 = sKV[(k0+tig)*KVS   + n0 + g];
            uint32_t b1 = sKV[(k0+4+tig)*KVS + n0 + g];
            mma8(acc[nt], a0, a1, a2, a3, b0, b1);
        }
    }
    __syncthreads();   // all sP (phi) reads done

    // o_pre = num * (1/(1e-5+den)) back into sP as tf32
    {
        float dn0 = sden[mt*16 + g], dn1 = sden[mt*16 + 8 + g];
#pragma unroll
        for (int nt = 0; nt < 8; nt++) {
            int col = nh*64 + nt*8 + 2*tig;
            int row = mt*16 + g;
            sP[row*PST + col]       = f2t(acc[nt][0]*dn0);
            sP[row*PST + col + 1]   = f2t(acc[nt][1]*dn0);
            sP[(row+8)*PST + col]   = f2t(acc[nt][2]*dn1);
            sP[(row+8)*PST + col+1] = f2t(acc[nt][3]*dn1);
        }
    }
    __syncthreads();

    // gemm2: o_l = o_pre @ W^T
    float ac2[8][4];
#pragma unroll
    for (int i = 0; i < 8; i++)
#pragma unroll
        for (int j = 0; j < 4; j++) ac2[i][j] = 0.f;
#pragma unroll
    for (int kk = 0; kk < 16; kk++) {
        int k0 = kk*8;
        const uint32_t* pa = sP + (mt*16+g)*PST + k0 + tig;
        uint32_t a0 = pa[0], a1 = pa[8*PST], a2 = pa[4], a3 = pa[8*PST+4];
#pragma unroll
        for (int nt = 0; nt < 8; nt++) {
            int n0 = nh*64 + nt*8;
            uint32_t b0 = sWt[(k0+tig)*WTS   + n0 + g];
            uint32_t b1 = sWt[(k0+4+tig)*WTS + n0 + g];
            mma8(ac2[nt], a0, a1, a2, a3, b0, b1);
        }
    }

    // out += o_l + bias
#pragma unroll
    for (int nt = 0; nt < 8; nt++) {
        int col = nh*64 + nt*8 + 2*tig;
        float b0 = bpr[col], b1 = bpr[col+1];
        float* op0 = out + qbase + (size_t)(mt*16+g)*DIM + col;
        float* op1 = out + qbase + (size_t)(mt*16+8+g)*DIM + col;
        float2 o0 = *(float2*)op0, o1 = *(float2*)op1;
        o0.x += ac2[nt][0] + b0; o0.y += ac2[nt][1] + b1;
        o1.x += ac2[nt][2] + b0; o1.y += ac2[nt][3] + b1;
        *(float2*)op0 = o0; *(float2*)op1 = o1;
    }
}

// ============================================================
extern "C" void kernel_launch(void* const* d_in, const int* in_sizes, int n_in,
                              void* d_out, int out_size) {
    const float* q = (const float*)d_in[0];
    const float* k = (const float*)d_in[1];
    const float* v = (const float*)d_in[2];
    const float* w = (const float*)d_in[3];
    const float* b = (const float*)d_in[4];
    float* out = (float*)d_out;

    int smKV = (2*128*PHS) * (int)sizeof(uint32_t);
    int sm3  = (64*QST + KVBUF + 64*SST + 64) * (int)sizeof(uint32_t);
    int sm5  = (DIM*KVS + DIM*WTS + 64*PST + 64 + 128) * (int)sizeof(uint32_t);
    cudaFuncSetAttribute(k_kvsum,  cudaFuncAttributeMaxDynamicSharedMemorySize, smKV);
    cudaFuncSetAttribute(k_sparse, cudaFuncAttributeMaxDynamicSharedMemorySize, sm3);
    cudaFuncSetAttribute(k_linear, cudaFuncAttributeMaxDynamicSharedMemorySize, sm5);

    k_blockmean<<<BHN*NB, DIM>>>(q, k);
    k_topk<<<BHN, 1024>>>();
    k_kvsum<<<NCH*BHN, 256, smKV>>>(k, v);
    k_reduce<<<(BHN*DIM*DIM)/256, 256>>>();
    k_sparse<<<BHN*NB, 256, sm3>>>(q, k, v, out);
    k_linear<<<BHN*NB, 256, sm5>>>(q, w, b, out);
}

// round 3
// speedup vs baseline: 3.2578x; 1.8078x over previous
#include <cuda_runtime.h>
#include <math.h>
#include <float.h>
#include <stdint.h>

#define BHN  32
#define LSEQ 2048
#define DIM  128
#define BLK  64
#define NB   32
#define TOP  4
#define NCH  16
#define CHL  (LSEQ/NCH)   // 128

// ---- scratch ----
__device__ float g_qt[(size_t)BHN*LSEQ*DIM];   // tf32-rounded copies
__device__ float g_kt[(size_t)BHN*LSEQ*DIM];
__device__ float g_vt[(size_t)BHN*LSEQ*DIM];
__device__ float g_qb[BHN*NB*DIM];
__device__ float g_kb[BHN*NB*DIM];
__device__ int   g_lut[BHN*NB*TOP];
__device__ float g_ksum[BHN*DIM];
__device__ float g_kv_part[(size_t)NCH*BHN*DIM*DIM];
__device__ float g_ksum_part[NCH*BHN*DIM];
__device__ float g_m[BHN*DIM*DIM];             // kv @ W^T, tf32-rounded

// ---- helpers ----
__device__ __forceinline__ uint32_t f2t(float f) {
    uint32_t r; asm("cvt.rna.tf32.f32 %0, %1;" : "=r"(r) : "f"(f)); return r;
}
__device__ __forceinline__ float4 t4(float4 a) {
    float4 r;
    r.x = __uint_as_float(f2t(a.x)); r.y = __uint_as_float(f2t(a.y));
    r.z = __uint_as_float(f2t(a.z)); r.w = __uint_as_float(f2t(a.w));
    return r;
}
__device__ __forceinline__ void mma8(float* c,
        uint32_t a0, uint32_t a1, uint32_t a2, uint32_t a3,
        uint32_t b0, uint32_t b1) {
    asm volatile(
        "mma.sync.aligned.m16n8k8.row.col.f32.tf32.tf32.f32 "
        "{%0,%1,%2,%3},{%4,%5,%6,%7},{%8,%9},{%0,%1,%2,%3};\n"
        : "+f"(c[0]), "+f"(c[1]), "+f"(c[2]), "+f"(c[3])
        : "r"(a0), "r"(a1), "r"(a2), "r"(a3), "r"(b0), "r"(b1));
}
__device__ __forceinline__ uint32_t s2u(const void* p) {
    uint32_t a;
    asm("{ .reg .u64 t; cvta.to.shared.u64 t, %1; cvt.u32.u64 %0, t; }" : "=r"(a) : "l"(p));
    return a;
}
__device__ __forceinline__ void cpa16(uint32_t s, const void* g) {
    asm volatile("cp.async.cg.shared.global [%0],[%1],16;\n" :: "r"(s), "l"(g));
}
#define CP_COMMIT() asm volatile("cp.async.commit_group;\n")
#define CP_WAIT(n)  asm volatile("cp.async.wait_group " #n ";\n")

// ============================================================
// K_prep: tf32 copies of q,k,v + exact block means of q,k
// grid = BHN*NB = 1024, 256 threads (64 rows per block)
// ============================================================
__global__ void __launch_bounds__(256) k_prep(const float4* __restrict__ q4,
                                              const float4* __restrict__ k4,
                                              const float4* __restrict__ v4) {
    __shared__ float redq[8][132];
    __shared__ float redk[8][132];
    int blk = blockIdx.x, tid = threadIdx.x;
    int c4 = tid & 31, rj = tid >> 5;
    size_t base = (size_t)blk * 64 * 32;
    float4* qt4 = (float4*)g_qt;
    float4* kt4 = (float4*)g_kt;
    float4* vt4 = (float4*)g_vt;

    float sq0=0,sq1=0,sq2=0,sq3=0, sk0=0,sk1=0,sk2=0,sk3=0;
#pragma unroll
    for (int i = 0; i < 8; i++) {
        size_t off = base + (size_t)(rj + 8*i)*32 + c4;
        float4 a = q4[off];
        sq0 += a.x; sq1 += a.y; sq2 += a.z; sq3 += a.w;
        qt4[off] = t4(a);
        float4 b = k4[off];
        sk0 += b.x; sk1 += b.y; sk2 += b.z; sk3 += b.w;
        kt4[off] = t4(b);
        vt4[off] = t4(v4[off]);
    }
    redq[rj][c4*4+0]=sq0; redq[rj][c4*4+1]=sq1; redq[rj][c4*4+2]=sq2; redq[rj][c4*4+3]=sq3;
    redk[rj][c4*4+0]=sk0; redk[rj][c4*4+1]=sk1; redk[rj][c4*4+2]=sk2; redk[rj][c4*4+3]=sk3;
    __syncthreads();
    if (tid < DIM) {
        float s = 0.f, t = 0.f;
#pragma unroll
        for (int j = 0; j < 8; j++) { s += redq[j][tid]; t += redk[j][tid]; }
        g_qb[blk*DIM + tid] = s * (1.f/BLK);
        g_kb[blk*DIM + tid] = t * (1.f/BLK);
    }
}

// ============================================================
// K2: blk_scores + top-4 (exact fp32, lowest-index tie-break)
// ============================================================
__global__ void k_topk() {
    __shared__ float sQ[NB][DIM];
    __shared__ float sK[NB][DIM+1];
    __shared__ float sS[NB][NB];
    int bh = blockIdx.x, tid = threadIdx.x;

    for (int i = tid; i < NB*DIM; i += 1024) {
        sQ[i>>7][i&127] = g_qb[bh*NB*DIM + i];
        sK[i>>7][i&127] = g_kb[bh*NB*DIM + i];
    }
    __syncthreads();
    {
        int qr = tid >> 5, kr = tid & 31;
        float acc = 0.f;
#pragma unroll 8
        for (int kk = 0; kk < DIM; kk++) acc += sQ[qr][kk] * sK[kr][kk];
        sS[qr][kr] = acc;
    }
    __syncthreads();

    int qr = tid >> 5, lane = tid & 31;
    float v = sS[qr][lane];
    int  mi = lane;
#pragma unroll
    for (int t = 0; t < TOP; t++) {
        float bv = v; int bi = mi;
#pragma unroll
        for (int off = 16; off; off >>= 1) {
            float ov = __shfl_xor_sync(0xffffffffu, bv, off);
            int   oi = __shfl_xor_sync(0xffffffffu, bi, off);
            if (ov > bv || (ov == bv && oi < bi)) { bv = ov; bi = oi; }
        }
        if (lane == 0) g_lut[(bh*NB + qr)*TOP + t] = bi;
        if (mi == bi) v = -FLT_MAX;
    }
}

// ============================================================
// K_kvsum: fused phi_k softmax + split-K kvsum = phi_k^T @ v
// grid = NCH*BHN = 512, 256 threads
// ============================================================
#define PHS 136
__global__ void __launch_bounds__(256) k_kvsum(const float* __restrict__ kin) {
    extern __shared__ uint32_t usm[];
    uint32_t* sPhi = usm;             // 128*PHS
    uint32_t* sV   = sPhi + 128*PHS;  // 128*PHS

    int bid = blockIdx.x;
    int ch  = bid >> 5, bh = bid & 31;
    int tid = threadIdx.x, lane = tid & 31, warp = tid >> 5;
    int g = lane >> 2, tig = lane & 3;
    size_t lbase = (size_t)bh*LSEQ + (size_t)ch*CHL;

    // prefetch V tile (already tf32) while computing phi
    {
        const float* vp = g_vt + lbase*DIM;
#pragma unroll
        for (int i = 0; i < 16; i++) {
            int idx = tid + 256*i;
            int r = idx >> 5, c = (idx & 31)*4;
            cpa16(s2u(sV + r*PHS + c), vp + r*DIM + c);
        }
        CP_COMMIT();
    }

    // phi_k rows (warp per row, 16 rows/warp), exact softmax on original k
    for (int i = 0; i < 16; i++) {
        int r = warp*16 + i;
        const float* src = kin + (lbase + r)*DIM;
        float x0 = src[lane], x1 = src[lane+32], x2 = src[lane+64], x3 = src[lane+96];
        float m = fmaxf(fmaxf(x0,x1), fmaxf(x2,x3));
#pragma unroll
        for (int o = 16; o; o >>= 1) m = fmaxf(m, __shfl_xor_sync(0xffffffffu, m, o));
        float e0 = __expf(x0-m), e1 = __expf(x1-m), e2 = __expf(x2-m), e3 = __expf(x3-m);
        float s = e0+e1+e2+e3;
#pragma unroll
        for (int o = 16; o; o >>= 1) s += __shfl_xor_sync(0xffffffffu, s, o);
        float inv = 1.f/s;
        uint32_t* dst = sPhi + r*PHS;
        dst[lane]    = f2t(e0*inv);
        dst[lane+32] = f2t(e1*inv);
        dst[lane+64] = f2t(e2*inv);
        dst[lane+96] = f2t(e3*inv);
    }
    CP_WAIT(0);
    __syncthreads();

    if (tid < DIM) {
        float s = 0.f;
#pragma unroll 8
        for (int r = 0; r < CHL; r++) s += __uint_as_float(sPhi[r*PHS + tid]);
        g_ksum_part[bid*DIM + tid] = s;
    }

    // GEMM: kv[d][e] += sum_l phi[l][d]*v[l][e]
    float acc[16][4];
#pragma unroll
    for (int i = 0; i < 16; i++)
#pragma unroll
        for (int j = 0; j < 4; j++) acc[i][j] = 0.f;

    int m0 = warp*16;
#pragma unroll
    for (int kk = 0; kk < 16; kk++) {
        int k0 = kk*8;
        uint32_t a0 = sPhi[(k0+tig)*PHS   + m0 + g];
        uint32_t a1 = sPhi[(k0+tig)*PHS   + m0 + 8 + g];
        uint32_t a2 = sPhi[(k0+4+tig)*PHS + m0 + g];
        uint32_t a3 = sPhi[(k0+4+tig)*PHS + m0 + 8 + g];
#pragma unroll
        for (int nt = 0; nt < 16; nt++) {
            int n0 = nt*8;
            uint32_t b0 = sV[(k0+tig)*PHS   + n0 + g];
            uint32_t b1 = sV[(k0+4+tig)*PHS + n0 + g];
            mma8(acc[nt], a0, a1, a2, a3, b0, b1);
        }
    }
    float* dst = g_kv_part + (size_t)bid*DIM*DIM;
#pragma unroll
    for (int nt = 0; nt < 16; nt++) {
        int col = nt*8 + 2*tig;
        int row = m0 + g;
        *(float2*)&dst[row*DIM + col]     = make_float2(acc[nt][0], acc[nt][1]);
        *(float2*)&dst[(row+8)*DIM + col] = make_float2(acc[nt][2], acc[nt][3]);
    }
}

// ============================================================
// K_kvw: reduce split-K partials, reduce ksum, M = kv @ W^T (tf32)
// grid = BHN = 32, 256 threads
// ============================================================
__global__ void __launch_bounds__(256) k_kvw(const float* __restrict__ w) {
    extern __shared__ uint32_t usm[];
    uint32_t* sKV = usm;               // 128*132
    uint32_t* sW  = sKV + DIM*132;     // 128*132

    int bh = blockIdx.x, tid = threadIdx.x;
    int lane = tid & 31, warp = tid >> 5;
    int g = lane >> 2, tig = lane & 3;

    for (int idx = tid; idx < DIM*DIM; idx += 256) {
        int e2 = idx >> 7, e = idx & 127;
        sW[e2*132 + e] = f2t(w[idx]);
        float s = 0.f;
#pragma unroll
        for (int ch = 0; ch < NCH; ch++)
            s += g_kv_part[(size_t)((ch<<5)|bh)*DIM*DIM + idx];
        sKV[(idx>>7)*132 + (idx&127)] = f2t(s);
    }
    if (tid < DIM) {
        float t = 0.f;
#pragma unroll
        for (int ch = 0; ch < NCH; ch++) t += g_ksum_part[((ch<<5)|bh)*DIM + tid];
        g_ksum[bh*DIM + tid] = t;
    }
    __syncthreads();

    // M[d][e2] = sum_e kv[d][e]*W[e2][e]
    float acc[16][4];
#pragma unroll
    for (int i = 0; i < 16; i++)
#pragma unroll
        for (int j = 0; j < 4; j++) acc[i][j] = 0.f;
    int m0 = warp*16;
#pragma unroll
    for (int kk = 0; kk < 16; kk++) {
        int k0 = kk*8;
        const uint32_t* pa = sKV + (m0+g)*132 + k0 + tig;
        uint32_t a0 = pa[0], a1 = pa[8*132], a2 = pa[4], a3 = pa[8*132+4];
#pragma unroll
        for (int nt = 0; nt < 16; nt++) {
            int n0 = nt*8;
            uint32_t b0 = sW[(n0+g)*132 + k0 + tig];
            uint32_t b1 = sW[(n0+g)*132 + k0 + 4 + tig];
            mma8(acc[nt], a0, a1, a2, a3, b0, b1);
        }
    }
    float* dst = g_m + bh*DIM*DIM;
#pragma unroll
    for (int nt = 0; nt < 16; nt++) {
        int col = nt*8 + 2*tig;
        int row = m0 + g;
        dst[row*DIM + col]     = __uint_as_float(f2t(acc[nt][0]));
        dst[row*DIM + col+1]   = __uint_as_float(f2t(acc[nt][1]));
        dst[(row+8)*DIM + col]   = __uint_as_float(f2t(acc[nt][2]));
        dst[(row+8)*DIM + col+1] = __uint_as_float(f2t(acc[nt][3]));
    }
}

// ============================================================
// K3: sparse attention, cp.async pipelined, tf32 mma
// grid = BHN*NB = 1024, 256 threads = 8 warps
// ============================================================
#define QSP 132
#define KSP 132
#define VSP 136
#define TBUF 8704    // 64*136 words per tile buffer
#define SST 260

__global__ void __launch_bounds__(256) k_sparse(float* __restrict__ out) {
    extern __shared__ uint32_t usm[];
    uint32_t* bufA = usm;
    uint32_t* bufB = usm + TBUF;
    uint32_t* bufC = usm + 2*TBUF;       // Q (stride 132), later a V buffer
    uint32_t* sS   = usm + 3*TBUF;       // 64*SST
    float*    sSf  = (float*)sS;
    float*    srow = (float*)(sS + 64*SST);
    __shared__ int slut[TOP];

    int bid = blockIdx.x, bh = bid >> 5, qb = bid & 31;
    int tid = threadIdx.x, lane = tid & 31, warp = tid >> 5;
    int g = lane >> 2, tig = lane & 3;
    int mt = warp & 3, ns = warp >> 2;

    if (tid < TOP) slut[tid] = g_lut[bid*TOP + tid];

    size_t qbase = ((size_t)bh*LSEQ + (size_t)qb*BLK)*DIM;
    // prefetch Q
    {
        const float* qp = g_qt + qbase;
#pragma unroll
        for (int i = 0; i < 8; i++) {
            int idx = tid + 256*i;
            int r = idx >> 5, c = (idx & 31)*4;
            cpa16(s2u(bufC + r*QSP + c), qp + r*DIM + c);
        }
        CP_COMMIT();
    }
    __syncthreads();   // slut visible

#define ISSUE_TILE(SRC, BUF, STRIDE, T)  do {                                  \
        size_t tb_ = ((size_t)bh*LSEQ + (size_t)slut[T]*BLK)*DIM;             \
        const float* tp_ = (SRC) + tb_;                                        \
        _Pragma("unroll")                                                      \
        for (int i_ = 0; i_ < 8; i_++) {                                       \
            int idx_ = tid + 256*i_;                                           \
            int r_ = idx_ >> 5, c_ = (idx_ & 31)*4;                            \
            cpa16(s2u((BUF) + r_*(STRIDE) + c_), tp_ + r_*DIM + c_);           \
        }                                                                      \
        CP_COMMIT();                                                           \
    } while (0)

    ISSUE_TILE(g_kt, bufA, KSP, 0);

    const float scale = 0.08838834764831845f;

    // ---- scores ----
    for (int t = 0; t < TOP; t++) {
        if (t < 3) ISSUE_TILE(g_kt, ((t+1)&1) ? bufB : bufA, KSP, t+1);
        else       ISSUE_TILE(g_vt, bufA, VSP, 0);
        CP_WAIT(1);
        __syncthreads();
        const uint32_t* sK = (t & 1) ? bufB : bufA;

        float acc[4][4];
#pragma unroll
        for (int i = 0; i < 4; i++)
#pragma unroll
            for (int j = 0; j < 4; j++) acc[i][j] = 0.f;
#pragma unroll
        for (int kk = 0; kk < 16; kk++) {
            int k0 = kk*8;
            const uint32_t* qa = bufC + (mt*16+g)*QSP + k0 + tig;
            uint32_t a0 = qa[0], a1 = qa[8*QSP], a2 = qa[4], a3 = qa[8*QSP+4];
#pragma unroll
            for (int nt = 0; nt < 4; nt++) {
                int n0 = ns*32 + nt*8;
                uint32_t b0 = sK[(n0+g)*KSP + k0 + tig];
                uint32_t b1 = sK[(n0+g)*KSP + k0 + 4 + tig];
                mma8(acc[nt], a0, a1, a2, a3, b0, b1);
            }
        }
#pragma unroll
        for (int nt = 0; nt < 4; nt++) {
            int col = t*64 + ns*32 + nt*8 + 2*tig;
            int row = mt*16 + g;
            *(float2*)&sSf[row*SST + col]     = make_float2(acc[nt][0]*scale, acc[nt][1]*scale);
            *(float2*)&sSf[(row+8)*SST + col] = make_float2(acc[nt][2]*scale, acc[nt][3]*scale);
        }
        __syncthreads();
    }

    // V1 -> bufC (Q dead), V2 -> bufB (K3 dead)
    ISSUE_TILE(g_vt, bufC, VSP, 1);
    ISSUE_TILE(g_vt, bufB, VSP, 2);

    // ---- softmax (4 threads per row) ----
    {
        int row = tid >> 2, sub = tid & 3;
        float* rp = sSf + row*SST;
        float m = -FLT_MAX;
#pragma unroll 8
        for (int jj = 0; jj < 64; jj++) m = fmaxf(m, rp[sub + jj*4]);
        m = fmaxf(m, __shfl_xor_sync(0xffffffffu, m, 1));
        m = fmaxf(m, __shfl_xor_sync(0xffffffffu, m, 2));
        float s = 0.f;
#pragma unroll 4
        for (int jj = 0; jj < 64; jj++) {
            int j = sub + jj*4;
            float e = __expf(rp[j] - m);
            s += e;
            sS[row*SST + j] = f2t(e);
        }
        s += __shfl_xor_sync(0xffffffffu, s, 1);
        s += __shfl_xor_sync(0xffffffffu, s, 2);
        if (sub == 0) srow[row] = 1.f/s;
    }
    __syncthreads();

    // ---- PV ----
    int nh = warp >> 2;
    float oac[8][4];
#pragma unroll
    for (int i = 0; i < 8; i++)
#pragma unroll
        for (int j = 0; j < 4; j++) oac[i][j] = 0.f;

#define PV_STEP(T, BUF)  do {                                                  \
        _Pragma("unroll")                                                      \
        for (int kk_ = 0; kk_ < 8; kk_++) {                                    \
            const uint32_t* pa_ = sS + (mt*16+g)*SST + (T)*64 + kk_*8 + tig;  \
            uint32_t a0_=pa_[0], a1_=pa_[8*SST], a2_=pa_[4], a3_=pa_[8*SST+4];\
            _Pragma("unroll")                                                  \
            for (int nt_ = 0; nt_ < 8; nt_++) {                                \
                int n0_ = nh*64 + nt_*8;                                       \
                uint32_t b0_ = (BUF)[(kk_*8+tig)*VSP + n0_ + g];               \
                uint32_t b1_ = (BUF)[(kk_*8+4+tig)*VSP + n0_ + g];             \
                mma8(oac[nt_], a0_, a1_, a2_, a3_, b0_, b1_);                  \
            }                                                                  \
        }                                                                      \
    } while (0)

    CP_WAIT(2); __syncthreads();
    PV_STEP(0, bufA);
    __syncthreads();
    ISSUE_TILE(g_vt, bufA, VSP, 3);
    CP_WAIT(2); __syncthreads();
    PV_STEP(1, bufC);
    CP_WAIT(1); __syncthreads();
    PV_STEP(2, bufB);
    CP_WAIT(0); __syncthreads();
    PV_STEP(3, bufA);

    float i0 = srow[mt*16 + g], i1 = srow[mt*16 + 8 + g];
#pragma unroll
    for (int nt = 0; nt < 8; nt++) {
        int col = nh*64 + nt*8 + 2*tig;
        float* op0 = out + qbase + (size_t)(mt*16+g)*DIM + col;
        float* op1 = out + qbase + (size_t)(mt*16+8+g)*DIM + col;
        *(float2*)op0 = make_float2(oac[nt][0]*i0, oac[nt][1]*i0);
        *(float2*)op1 = make_float2(oac[nt][2]*i1, oac[nt][3]*i1);
    }
}

// ============================================================
// K5: linear half: phi_q softmax + one GEMM (phi_q @ M); out += .
// grid = BHN*NB = 1024, 256 threads, ~104 KB smem -> 2 blocks/SM
// ============================================================
#define MSP 136
#define PSP 132

__global__ void __launch_bounds__(256) k_linear(const float* __restrict__ q,
                                                const float* __restrict__ bpr,
                                                float* __restrict__ out) {
    extern __shared__ uint32_t usm[];
    uint32_t* sM = usm;                    // 128*MSP
    uint32_t* sP = sM + DIM*MSP;           // 64*PSP
    float* sden = (float*)(sP + 64*PSP);   // 64
    float* sks  = sden + 64;               // 128

    int bid = blockIdx.x, bh = bid >> 5, qb = bid & 31;
    int tid = threadIdx.x, lane = tid & 31, warp = tid >> 5;
    int g = lane >> 2, tig = lane & 3;
    int mt = warp & 3, nh = warp >> 2;

    // prefetch M tile
    {
        const float* mp = g_m + bh*DIM*DIM;
#pragma unroll
        for (int i = 0; i < 16; i++) {
            int idx = tid + 256*i;
            int r = idx >> 5, c = (idx & 31)*4;
            cpa16(s2u(sM + r*MSP + c), mp + r*DIM + c);
        }
        CP_COMMIT();
    }
    if (tid < DIM) sks[tid] = g_ksum[bh*DIM + tid];
    __syncthreads();

    // phi_q softmax + den (exact, from original q)
    size_t qbase = ((size_t)bh*LSEQ + (size_t)qb*BLK)*DIM;
    for (int r = warp; r < BLK; r += 8) {
        const float* src = q + qbase + (size_t)r*DIM;
        float x0 = src[lane], x1 = src[lane+32], x2 = src[lane+64], x3 = src[lane+96];
        float m = fmaxf(fmaxf(x0,x1), fmaxf(x2,x3));
#pragma unroll
        for (int o = 16; o; o >>= 1) m = fmaxf(m, __shfl_xor_sync(0xffffffffu, m, o));
        float e0 = __expf(x0-m), e1 = __expf(x1-m), e2 = __expf(x2-m), e3 = __expf(x3-m);
        float s = e0+e1+e2+e3;
#pragma unroll
        for (int o = 16; o; o >>= 1) s += __shfl_xor_sync(0xffffffffu, s, o);
        float inv = 1.f/s;
        e0 *= inv; e1 *= inv; e2 *= inv; e3 *= inv;
        float dp = e0*sks[lane] + e1*sks[lane+32] + e2*sks[lane+64] + e3*sks[lane+96];
#pragma unroll
        for (int o = 16; o; o >>= 1) dp += __shfl_xor_sync(0xffffffffu, dp, o);
        uint32_t* dst = sP + r*PSP;
        dst[lane]    = f2t(e0);
        dst[lane+32] = f2t(e1);
        dst[lane+64] = f2t(e2);
        dst[lane+96] = f2t(e3);
        if (lane == 0) sden[r] = 1.f/(1e-5f + dp);
    }
    CP_WAIT(0);
    __syncthreads();

    // GEMM: o_pre = phi_q @ M
    float acc[8][4];
#pragma unroll
    for (int i = 0; i < 8; i++)
#pragma unroll
        for (int j = 0; j < 4; j++) acc[i][j] = 0.f;
#pragma unroll
    for (int kk = 0; kk < 16; kk++) {
        int k0 = kk*8;
        const uint32_t* pa = sP + (mt*16+g)*PSP + k0 + tig;
        uint32_t a0 = pa[0], a1 = pa[8*PSP], a2 = pa[4], a3 = pa[8*PSP+4];
#pragma unroll
        for (int nt = 0; nt < 8; nt++) {
            int n0 = nh*64 + nt*8;
            uint32_t b0 = sM[(k0+tig)*MSP + n0 + g];
            uint32_t b1 = sM[(k0+4+tig)*MSP + n0 + g];
            mma8(acc[nt], a0, a1, a2, a3, b0, b1);
        }
    }

    float dn0 = sden[mt*16 + g], dn1 = sden[mt*16 + 8 + g];
#pragma unroll
    for (int nt = 0; nt < 8; nt++) {
        int col = nh*64 + nt*8 + 2*tig;
        float b0 = bpr[col], b1 = bpr[col+1];
        float* op0 = out + qbase + (size_t)(mt*16+g)*DIM + col;
        float* op1 = out + qbase + (size_t)(mt*16+8+g)*DIM + col;
        float2 o0 = *(float2*)op0, o1 = *(float2*)op1;
        o0.x += acc[nt][0]*dn0 + b0; o0.y += acc[nt][1]*dn0 + b1;
        o1.x += acc[nt][2]*dn1 + b0; o1.y += acc[nt][3]*dn1 + b1;
        *(float2*)op0 = o0; *(float2*)op1 = o1;
    }
}

// ============================================================
extern "C" void kernel_launch(void* const* d_in, const int* in_sizes, int n_in,
                              void* d_out, int out_size) {
    const float* q = (const float*)d_in[0];
    const float* k = (const float*)d_in[1];
    const float* v = (const float*)d_in[2];
    const float* w = (const float*)d_in[3];
    const float* b = (const float*)d_in[4];
    float* out = (float*)d_out;

    int smKV  = (2*128*PHS) * 4;
    int smKVW = (2*128*132) * 4;
    int sm3   = (3*TBUF + 64*SST + 64) * 4;
    int sm5   = (DIM*MSP + 64*PSP + 64 + 128) * 4;
    cudaFuncSetAttribute(k_kvsum,  cudaFuncAttributeMaxDynamicSharedMemorySize, smKV);
    cudaFuncSetAttribute(k_kvw,    cudaFuncAttributeMaxDynamicSharedMemorySize, smKVW);
    cudaFuncSetAttribute(k_sparse, cudaFuncAttributeMaxDynamicSharedMemorySize, sm3);
    cudaFuncSetAttribute(k_linear, cudaFuncAttributeMaxDynamicSharedMemorySize, sm5);

    k_prep<<<BHN*NB, 256>>>((const float4*)q, (const float4*)k, (const float4*)v);
    k_topk<<<BHN, 1024>>>();
    k_kvsum<<<NCH*BHN, 256, smKV>>>(k);
    k_kvw<<<BHN, 256, smKVW>>>(w);
    k_sparse<<<BHN*NB, 256, sm3>>>(out);
    k_linear<<<BHN*NB, 256, sm5>>>(q, b, out);
}

// round 5
// speedup vs baseline: 4.8267x; 1.4816x over previous
#include <cuda_runtime.h>
#include <cuda_fp16.h>
#include <math.h>
#include <float.h>
#include <stdint.h>

#define BHN  32
#define LSEQ 2048
#define DIM  128
#define BLK  64
#define NB   32
#define TOP  4
#define NCH  16
#define CHL  (LSEQ/NCH)   // 128

// ---- scratch ----
__device__ __half g_qh[(size_t)BHN*LSEQ*DIM];   // fp16 q [bh][l][d]
__device__ __half g_kh[(size_t)BHN*LSEQ*DIM];   // fp16 k [bh][l][d]
__device__ __half g_vth[(size_t)BHN*DIM*LSEQ];  // fp16 v transposed [bh][d][l]
__device__ float  g_qb[BHN*NB*DIM];
__device__ float  g_kb[BHN*NB*DIM];
__device__ int    g_lut[BHN*NB*TOP];
__device__ float  g_ksum[BHN*DIM];
__device__ float  g_kv_part[(size_t)NCH*BHN*DIM*DIM];
__device__ float  g_ksum_part[NCH*BHN*DIM];
__device__ __half g_mt[BHN*DIM*DIM];            // (kv@W^T)^T : [bh][e2][d]

// ---- helpers ----
__device__ __forceinline__ uint32_t h2(float a, float b) {
    __half2 h = __floats2half2_rn(a, b);
    return *(uint32_t*)&h;
}
__device__ __forceinline__ void mma16(float* c,
        uint32_t a0, uint32_t a1, uint32_t a2, uint32_t a3,
        uint32_t b0, uint32_t b1) {
    asm volatile(
        "mma.sync.aligned.m16n8k16.row.col.f32.f16.f16.f32 "
        "{%0,%1,%2,%3},{%4,%5,%6,%7},{%8,%9},{%0,%1,%2,%3};\n"
        : "+f"(c[0]), "+f"(c[1]), "+f"(c[2]), "+f"(c[3])
        : "r"(a0), "r"(a1), "r"(a2), "r"(a3), "r"(b0), "r"(b1));
}
__device__ __forceinline__ uint32_t s2u(const void* p) {
    uint32_t a;
    asm("{ .reg .u64 t; cvta.to.shared.u64 t, %1; cvt.u32.u64 %0, t; }" : "=r"(a) : "l"(p));
    return a;
}
__device__ __forceinline__ void cpa16(uint32_t s, const void* g) {
    asm volatile("cp.async.cg.shared.global [%0],[%1],16;\n" :: "r"(s), "l"(g));
}
#define CP_COMMIT() asm volatile("cp.async.commit_group;\n")
#define CP_WAIT(n)  asm volatile("cp.async.wait_group " #n ";\n")

#define LDA4(PTR, STR) \
    a0 = *(const uint32_t*)(PTR); a1 = *(const uint32_t*)((PTR) + 8*(STR)); \
    a2 = *(const uint32_t*)((PTR) + 8); a3 = *(const uint32_t*)((PTR) + 8*(STR) + 8)
#define LDB2(PTR) \
    b0 = *(const uint32_t*)(PTR); b1 = *(const uint32_t*)((PTR) + 8)

// ============================================================
// K_prep: fp16 copies of q,k (natural) and v (transposed) + exact block means
// grid = BHN*NB = 1024, 256 threads
// ============================================================
__global__ void __launch_bounds__(256) k_prep(const float4* __restrict__ q4,
                                              const float4* __restrict__ k4,
                                              const float4* __restrict__ v4) {
    __shared__ float redq[8][132];
    __shared__ float redk[8][132];
    __shared__ __align__(16) __half sVt[128][80];   // 160B rows: 16B aligned
    int blk = blockIdx.x, tid = threadIdx.x;
    int c4 = tid & 31, rj = tid >> 5;
    size_t base = (size_t)blk * 64 * 32;
    uint2* qh2 = (uint2*)g_qh;
    uint2* kh2 = (uint2*)g_kh;

    float sq0=0,sq1=0,sq2=0,sq3=0, sk0=0,sk1=0,sk2=0,sk3=0;
#pragma unroll
    for (int i = 0; i < 8; i++) {
        int r = rj + 8*i;
        size_t off = base + (size_t)r*32 + c4;
        float4 a = q4[off];
        sq0+=a.x; sq1+=a.y; sq2+=a.z; sq3+=a.w;
        uint2 ua; ua.x = h2(a.x,a.y); ua.y = h2(a.z,a.w);
        qh2[off] = ua;
        float4 b = k4[off];
        sk0+=b.x; sk1+=b.y; sk2+=b.z; sk3+=b.w;
        uint2 ub; ub.x = h2(b.x,b.y); ub.y = h2(b.z,b.w);
        kh2[off] = ub;
        float4 c = v4[off];
        sVt[c4*4+0][r] = __float2half_rn(c.x);
        sVt[c4*4+1][r] = __float2half_rn(c.y);
        sVt[c4*4+2][r] = __float2half_rn(c.z);
        sVt[c4*4+3][r] = __float2half_rn(c.w);
    }
    redq[rj][c4*4+0]=sq0; redq[rj][c4*4+1]=sq1; redq[rj][c4*4+2]=sq2; redq[rj][c4*4+3]=sq3;
    redk[rj][c4*4+0]=sk0; redk[rj][c4*4+1]=sk1; redk[rj][c4*4+2]=sk2; redk[rj][c4*4+3]=sk3;
    __syncthreads();
    if (tid < DIM) {
        float s = 0.f, t = 0.f;
#pragma unroll
        for (int j = 0; j < 8; j++) { s += redq[j][tid]; t += redk[j][tid]; }
        g_qb[blk*DIM + tid] = s * (1.f/BLK);
        g_kb[blk*DIM + tid] = t * (1.f/BLK);
        // write transposed V row d=tid: 64 halves = 8 x uint4
        int bh = blk >> 5, qb = blk & 31;
        const uint4* srcr = (const uint4*)&sVt[tid][0];
        uint4* dstr = (uint4*)(g_vth + ((size_t)(bh*DIM + tid))*LSEQ + qb*64);
#pragma unroll
        for (int j = 0; j < 8; j++) dstr[j] = srcr[j];
    }
}

// ============================================================
// K2: blk_scores + top-4 (exact fp32, lowest-index tie-break)
// ============================================================
__global__ void k_topk() {
    __shared__ float sQ[NB][DIM];
    __shared__ float sK[NB][DIM+1];
    __shared__ float sS[NB][NB];
    int bh = blockIdx.x, tid = threadIdx.x;

    for (int i = tid; i < NB*DIM; i += 1024) {
        sQ[i>>7][i&127] = g_qb[bh*NB*DIM + i];
        sK[i>>7][i&127] = g_kb[bh*NB*DIM + i];
    }
    __syncthreads();
    {
        int qr = tid >> 5, kr = tid & 31;
        float acc = 0.f;
#pragma unroll 8
        for (int kk = 0; kk < DIM; kk++) acc += sQ[qr][kk] * sK[kr][kk];
        sS[qr][kr] = acc;
    }
    __syncthreads();

    int qr = tid >> 5, lane = tid & 31;
    float v = sS[qr][lane];
    int  mi = lane;
#pragma unroll
    for (int t = 0; t < TOP; t++) {
        float bv = v; int bi = mi;
#pragma unroll
        for (int off = 16; off; off >>= 1) {
            float ov = __shfl_xor_sync(0xffffffffu, bv, off);
            int   oi = __shfl_xor_sync(0xffffffffu, bi, off);
            if (ov > bv || (ov == bv && oi < bi)) { bv = ov; bi = oi; }
        }
        if (lane == 0) g_lut[(bh*NB + qr)*TOP + t] = bi;
        if (mi == bi) v = -FLT_MAX;
    }
}

// ============================================================
// K_kvsum: fused phi_k softmax (transposed into smem) + split-K phi^T@V
// grid = NCH*BHN = 512, 256 threads, fp16 mma
// ============================================================
#define KVS 136
__global__ void __launch_bounds__(256) k_kvsum(const float* __restrict__ kin) {
    extern __shared__ __half hsm[];
    __half* sPhiT = hsm;               // [128 d][136 l]
    __half* sVt   = hsm + 128*KVS;     // [128 e][136 l]

    int bid = blockIdx.x;
    int ch  = bid >> 5, bh = bid & 31;
    int tid = threadIdx.x, lane = tid & 31, warp = tid >> 5;
    int g = lane >> 2, tig = lane & 3;
    size_t lbase = (size_t)bh*LSEQ + (size_t)ch*CHL;

    {
        const __half* vp = g_vth + (size_t)bh*DIM*LSEQ + (size_t)ch*CHL;
#pragma unroll
        for (int i = 0; i < 8; i++) {
            int idx = tid + 256*i;
            int r = idx >> 4, c8 = (idx & 15)*8;
            cpa16(s2u(sVt + r*KVS + c8), vp + (size_t)r*LSEQ + c8);
        }
        CP_COMMIT();
    }

    for (int i = 0; i < 16; i++) {
        int r = warp*16 + i;
        const float* src = kin + (lbase + r)*DIM;
        float x0 = src[lane], x1 = src[lane+32], x2 = src[lane+64], x3 = src[lane+96];
        float m = fmaxf(fmaxf(x0,x1), fmaxf(x2,x3));
#pragma unroll
        for (int o = 16; o; o >>= 1) m = fmaxf(m, __shfl_xor_sync(0xffffffffu, m, o));
        float e0 = __expf(x0-m), e1 = __expf(x1-m), e2 = __expf(x2-m), e3 = __expf(x3-m);
        float s = e0+e1+e2+e3;
#pragma unroll
        for (int o = 16; o; o >>= 1) s += __shfl_xor_sync(0xffffffffu, s, o);
        float inv = 1.f/s;
        sPhiT[(lane)*KVS    + r] = __float2half_rn(e0*inv);
        sPhiT[(lane+32)*KVS + r] = __float2half_rn(e1*inv);
        sPhiT[(lane+64)*KVS + r] = __float2half_rn(e2*inv);
        sPhiT[(lane+96)*KVS + r] = __float2half_rn(e3*inv);
    }
    CP_WAIT(0);
    __syncthreads();

    if (tid < DIM) {
        const __half2* p = (const __half2*)(sPhiT + tid*KVS);
        float s = 0.f;
#pragma unroll 16
        for (int j = 0; j < 64; j++) { float2 f = __half22float2(p[j]); s += f.x + f.y; }
        g_ksum_part[bid*DIM + tid] = s;
    }

    float acc[16][4];
#pragma unroll
    for (int i = 0; i < 16; i++)
#pragma unroll
        for (int j = 0; j < 4; j++) acc[i][j] = 0.f;
    int m0 = warp*16;
    uint32_t a0,a1,a2,a3,b0,b1;
#pragma unroll
    for (int kk = 0; kk < 8; kk++) {
        int k0 = kk*16;
        const __half* ap = sPhiT + (m0+g)*KVS + k0 + 2*tig;
        LDA4(ap, KVS);
#pragma unroll
        for (int nt = 0; nt < 16; nt++) {
            const __half* bp = sVt + (nt*8+g)*KVS + k0 + 2*tig;
            LDB2(bp);
            mma16(acc[nt], a0,a1,a2,a3, b0,b1);
        }
    }
    float* dst = g_kv_part + (size_t)bid*DIM*DIM;
#pragma unroll
    for (int nt = 0; nt < 16; nt++) {
        int col = nt*8 + 2*tig;
        int row = m0 + g;
        *(float2*)&dst[row*DIM + col]     = make_float2(acc[nt][0], acc[nt][1]);
        *(float2*)&dst[(row+8)*DIM + col] = make_float2(acc[nt][2], acc[nt][3]);
    }
}

// ============================================================
// K_kvw: reduce split-K partials + M^T = (kv @ W^T)^T fp16
// grid = BHN*4 = 128, 256 threads; each block owns 32 kv rows
// ============================================================
__global__ void __launch_bounds__(256) k_kvw(const float4* __restrict__ w4) {
    extern __shared__ __half hsm[];
    __half* sKV = hsm;              // [32 d][136 e]
    __half* sW  = hsm + 32*KVS;     // [128 e2][136 e]

    int bh = blockIdx.x >> 2, part = blockIdx.x & 3;
    int m0g = part*32;
    int tid = threadIdx.x, lane = tid & 31, warp = tid >> 5;
    int g = lane >> 2, tig = lane & 3;

    for (int idx = tid; idx < 32*DIM; idx += 256) {
        int d = idx >> 7, e = idx & 127;
        float s = 0.f;
#pragma unroll
        for (int ch = 0; ch < NCH; ch++)
            s += g_kv_part[(size_t)((ch<<5)|bh)*DIM*DIM + (m0g+d)*DIM + e];
        sKV[d*KVS + e] = __float2half_rn(s);
    }
    for (int i4 = tid; i4 < 4096; i4 += 256) {
        int e2 = i4 >> 5, ec = (i4 & 31)*4;
        float4 wv = w4[i4];
        *(uint32_t*)(sW + e2*KVS + ec)     = h2(wv.x, wv.y);
        *(uint32_t*)(sW + e2*KVS + ec + 2) = h2(wv.z, wv.w);
    }
    if (part == 0 && tid < DIM) {
        float t = 0.f;
#pragma unroll
        for (int ch = 0; ch < NCH; ch++) t += g_ksum_part[((ch<<5)|bh)*DIM + tid];
        g_ksum[bh*DIM + tid] = t;
    }
    __syncthreads();

    int mt = warp & 1, ng = warp >> 1;
    int m0 = mt*16;
    float acc[4][4];
#pragma unroll
    for (int i = 0; i < 4; i++)
#pragma unroll
        for (int j = 0; j < 4; j++) acc[i][j] = 0.f;
    uint32_t a0,a1,a2,a3,b0,b1;
#pragma unroll
    for (int kk = 0; kk < 8; kk++) {
        int k0 = kk*16;
        const __half* ap = sKV + (m0+g)*KVS + k0 + 2*tig;
        LDA4(ap, KVS);
#pragma unroll
        for (int nt = 0; nt < 4; nt++) {
            const __half* bp = sW + (ng*32 + nt*8 + g)*KVS + k0 + 2*tig;
            LDB2(bp);
            mma16(acc[nt], a0,a1,a2,a3, b0,b1);
        }
    }
    __half* dst = g_mt + (size_t)bh*DIM*DIM;
    int row = m0g + m0 + g;
#pragma unroll
    for (int nt = 0; nt < 4; nt++) {
        int col = ng*32 + nt*8 + 2*tig;
        dst[col*DIM + row]         = __float2half_rn(acc[nt][0]);
        dst[(col+1)*DIM + row]     = __float2half_rn(acc[nt][1]);
        dst[col*DIM + row + 8]     = __float2half_rn(acc[nt][2]);
        dst[(col+1)*DIM + row + 8] = __float2half_rn(acc[nt][3]);
    }
}

// ============================================================
// K_fused: sparse attention (regs softmax) + linear half, fp16 mma
// grid = BHN*NB = 1024, 256 threads, 114432B smem -> 2 blocks/SM
// half-offsets: sQ 0 (64x136), bufs @8704/18944/29184 (128x80 each),
// sP @39424 (64x264), stats @56320. Mt later occupies [0..17408).
// ============================================================
#define B0 8704
#define B1 18944
#define B2 29184
#define SPO 39424
#define PST2 264
#define STATS 56320
#define VSTR 80

__global__ void __launch_bounds__(256,2) k_fused(const float* __restrict__ q,
                                                 const float* __restrict__ bpr,
                                                 float* __restrict__ out) {
    extern __shared__ __half hsm[];
    __half* sQ = hsm;
    __half* sP = hsm + SPO;
    float* swmax = (float*)(hsm + STATS);   // [64][2]
    float* swsum = swmax + 128;             // [64][2]
    float* sks   = swsum + 128;             // [128]
    float* sden  = sks + 128;               // [64]

    int bid = blockIdx.x, bh = bid >> 5, qb = bid & 31;
    int tid = threadIdx.x, lane = tid & 31, warp = tid >> 5;
    int g = lane >> 2, tig = lane & 3;
    int mt = warp & 3, ns = warp >> 2;

    int lut[4];
#pragma unroll
    for (int t = 0; t < TOP; t++) lut[t] = g_lut[bid*TOP + t];
    if (tid < DIM) sks[tid] = g_ksum[bh*DIM + tid];

#define ISSUE64(SRC, DST) do {                                          \
        const __half* s_ = (SRC);                                       \
        _Pragma("unroll")                                               \
        for (int i_ = 0; i_ < 4; i_++) {                                \
            int idx_ = tid + 256*i_;                                    \
            int r_ = idx_ >> 4, c_ = (idx_ & 15)*8;                     \
            cpa16(s2u((DST) + r_*136 + c_), s_ + r_*128 + c_);          \
        }                                                               \
    } while (0)
#define ISSUE_VT(T, DST) do {                                           \
        const __half* s_ = g_vth + (size_t)bh*DIM*LSEQ + lut[T]*64;     \
        _Pragma("unroll")                                               \
        for (int i_ = 0; i_ < 4; i_++) {                                \
            int idx_ = tid + 256*i_;                                    \
            int r_ = idx_ >> 3, c_ = (idx_ & 7)*8;                      \
            cpa16(s2u((DST) + r_*VSTR + c_), s_ + (size_t)r_*LSEQ + c_);\
        }                                                               \
    } while (0)

    size_t qh_base = ((size_t)bh*LSEQ + (size_t)qb*BLK)*DIM;
    ISSUE64(g_qh + qh_base, sQ);
    ISSUE64(g_kh + ((size_t)bh*LSEQ + lut[0]*BLK)*DIM, hsm + B0);
    CP_COMMIT();
    ISSUE64(g_kh + ((size_t)bh*LSEQ + lut[1]*BLK)*DIM, hsm + B1);
    CP_COMMIT();
    ISSUE64(g_kh + ((size_t)bh*LSEQ + lut[2]*BLK)*DIM, hsm + B2);
    CP_COMMIT();

    float accS[4][4][4];
#pragma unroll
    for (int t = 0; t < 4; t++)
#pragma unroll
        for (int i = 0; i < 4; i++)
#pragma unroll
            for (int j = 0; j < 4; j++) accS[t][i][j] = 0.f;

    uint32_t a0,a1,a2,a3,b0,b1;

#define MMA_S(T, KB) do {                                               \
        _Pragma("unroll")                                               \
        for (int kk = 0; kk < 8; kk++) {                                \
            int k0 = kk*16;                                             \
            const __half* ap = sQ + (mt*16+g)*136 + k0 + 2*tig;         \
            LDA4(ap, 136);                                              \
            _Pragma("unroll")                                           \
            for (int nt = 0; nt < 4; nt++) {                            \
                const __half* bp = (KB) + (ns*32+nt*8+g)*136 + k0 + 2*tig; \
                LDB2(bp);                                               \
                mma16(accS[T][nt], a0,a1,a2,a3, b0,b1);                 \
            }                                                           \
        }                                                               \
    } while (0)

    CP_WAIT(2); __syncthreads();
    MMA_S(0, hsm + B0); __syncthreads();
    ISSUE64(g_kh + ((size_t)bh*LSEQ + lut[3]*BLK)*DIM, hsm + B0); CP_COMMIT();
    CP_WAIT(2); __syncthreads();
    MMA_S(1, hsm + B1); __syncthreads();
    ISSUE_VT(0, hsm + B1); CP_COMMIT();
    CP_WAIT(2); __syncthreads();
    MMA_S(2, hsm + B2); __syncthreads();
    ISSUE_VT(1, hsm + B2); CP_COMMIT();
    CP_WAIT(2); __syncthreads();
    MMA_S(3, hsm + B0); __syncthreads();
    ISSUE_VT(2, hsm + B0); CP_COMMIT();

    // ---- softmax over registers with cross-warp stats ----
    const float scale = 0.08838834764831845f;
    int row0 = mt*16 + g, row1 = row0 + 8;
    {
        float m0v = -FLT_MAX, m1v = -FLT_MAX;
#pragma unroll
        for (int t = 0; t < 4; t++)
#pragma unroll
            for (int nt = 0; nt < 4; nt++) {
                m0v = fmaxf(m0v, fmaxf(accS[t][nt][0], accS[t][nt][1]));
                m1v = fmaxf(m1v, fmaxf(accS[t][nt][2], accS[t][nt][3]));
            }
        m0v = fmaxf(m0v, __shfl_xor_sync(0xffffffffu, m0v, 1));
        m0v = fmaxf(m0v, __shfl_xor_sync(0xffffffffu, m0v, 2));
        m1v = fmaxf(m1v, __shfl_xor_sync(0xffffffffu, m1v, 1));
        m1v = fmaxf(m1v, __shfl_xor_sync(0xffffffffu, m1v, 2));
        if (tig == 0) { swmax[row0*2+ns] = m0v; swmax[row1*2+ns] = m1v; }
    }
    __syncthreads();
    {
        float gm0 = fmaxf(swmax[row0*2], swmax[row0*2+1]);
        float gm1 = fmaxf(swmax[row1*2], swmax[row1*2+1]);
        float s0 = 0.f, s1 = 0.f;
#pragma unroll
        for (int t = 0; t < 4; t++)
#pragma unroll
            for (int nt = 0; nt < 4; nt++) {
                float e0 = __expf((accS[t][nt][0]-gm0)*scale);
                float e1 = __expf((accS[t][nt][1]-gm0)*scale);
                float e2 = __expf((accS[t][nt][2]-gm1)*scale);
                float e3 = __expf((accS[t][nt][3]-gm1)*scale);
                s0 += e0 + e1; s1 += e2 + e3;
                int col = t*64 + ns*32 + nt*8 + 2*tig;
                *(uint32_t*)(sP + row0*PST2 + col) = h2(e0, e1);
                *(uint32_t*)(sP + row1*PST2 + col) = h2(e2, e3);
            }
        s0 += __shfl_xor_sync(0xffffffffu, s0, 1);
        s0 += __shfl_xor_sync(0xffffffffu, s0, 2);
        s1 += __shfl_xor_sync(0xffffffffu, s1, 1);
        s1 += __shfl_xor_sync(0xffffffffu, s1, 2);
        if (tig == 0) { swsum[row0*2+ns] = s0; swsum[row1*2+ns] = s1; }
    }

    // ---- PV ----
    float oac[8][4];
#pragma unroll
    for (int i = 0; i < 8; i++)
#pragma unroll
        for (int j = 0; j < 4; j++) oac[i][j] = 0.f;

#define MMA_PV(T, VB) do {                                              \
        _Pragma("unroll")                                               \
        for (int kk = 0; kk < 4; kk++) {                                \
            const __half* ap = sP + (mt*16+g)*PST2 + (T)*64 + kk*16 + 2*tig; \
            LDA4(ap, PST2);                                             \
            _Pragma("unroll")                                           \
            for (int nt = 0; nt < 8; nt++) {                            \
                const __half* bp = (VB) + (ns*64+nt*8+g)*VSTR + kk*16 + 2*tig; \
                LDB2(bp);                                               \
                mma16(oac[nt], a0,a1,a2,a3, b0,b1);                     \
            }                                                           \
        }                                                               \
    } while (0)

    CP_WAIT(2); __syncthreads();
    MMA_PV(0, hsm + B1); __syncthreads();
    ISSUE_VT(3, hsm + B1); CP_COMMIT();
    CP_WAIT(2); __syncthreads();
    MMA_PV(1, hsm + B2); __syncthreads();
    CP_WAIT(1); __syncthreads();
    MMA_PV(2, hsm + B0);
    __syncthreads();   // B0/sQ region dead across ALL warps before Mt overwrite
    // load M^T into [0 .. 128*136) region (sQ + B0 dead)
    {
        const __half* s_ = g_mt + (size_t)bh*DIM*DIM;
#pragma unroll
        for (int i_ = 0; i_ < 8; i_++) {
            int idx_ = tid + 256*i_;
            int r_ = idx_ >> 4, c_ = (idx_ & 15)*8;
            cpa16(s2u(hsm + r_*136 + c_), s_ + r_*128 + c_);
        }
        CP_COMMIT();
    }
    CP_WAIT(1); __syncthreads();
    MMA_PV(3, hsm + B1);

    // ---- phi_q (exact) into B2 + den ----
    for (int r = warp; r < BLK; r += 8) {
        const float* src = q + ((size_t)bh*LSEQ + (size_t)qb*BLK + r)*DIM;
        float x0 = src[lane], x1 = src[lane+32], x2 = src[lane+64], x3 = src[lane+96];
        float m = fmaxf(fmaxf(x0,x1), fmaxf(x2,x3));
#pragma unroll
        for (int o = 16; o; o >>= 1) m = fmaxf(m, __shfl_xor_sync(0xffffffffu, m, o));
        float e0 = __expf(x0-m), e1 = __expf(x1-m), e2 = __expf(x2-m), e3 = __expf(x3-m);
        float s = e0+e1+e2+e3;
#pragma unroll
        for (int o = 16; o; o >>= 1) s += __shfl_xor_sync(0xffffffffu, s, o);
        float inv = 1.f/s;
        e0 *= inv; e1 *= inv; e2 *= inv; e3 *= inv;
        float dp = e0*sks[lane] + e1*sks[lane+32] + e2*sks[lane+64] + e3*sks[lane+96];
#pragma unroll
        for (int o = 16; o; o >>= 1) dp += __shfl_xor_sync(0xffffffffu, dp, o);
        __half* dst = hsm + B2 + r*136;
        dst[lane]    = __float2half_rn(e0);
        dst[lane+32] = __float2half_rn(e1);
        dst[lane+64] = __float2half_rn(e2);
        dst[lane+96] = __float2half_rn(e3);
        if (lane == 0) sden[r] = 1.f/(1e-5f + dp);
    }
    CP_WAIT(0);
    __syncthreads();

    // ---- linear GEMM: o_pre = phi_q @ M  (A = B2, B = Mt @ base) ----
    float acc2[8][4];
#pragma unroll
    for (int i = 0; i < 8; i++)
#pragma unroll
        for (int j = 0; j < 4; j++) acc2[i][j] = 0.f;
#pragma unroll
    for (int kk = 0; kk < 8; kk++) {
        int k0 = kk*16;
        const __half* ap = hsm + B2 + (mt*16+g)*136 + k0 + 2*tig;
        LDA4(ap, 136);
#pragma unroll
        for (int nt = 0; nt < 8; nt++) {
            const __half* bp = hsm + (ns*64+nt*8+g)*136 + k0 + 2*tig;
            LDB2(bp);
            mma16(acc2[nt], a0,a1,a2,a3, b0,b1);
        }
    }

    // ---- epilogue: out = o_s + o_l + bias (single write) ----
    float inv0 = 1.f/(swsum[row0*2] + swsum[row0*2+1]);
    float inv1 = 1.f/(swsum[row1*2] + swsum[row1*2+1]);
    float dn0 = sden[row0], dn1 = sden[row1];
    size_t obase = ((size_t)bh*LSEQ + (size_t)qb*BLK)*DIM;
#pragma unroll
    for (int nt = 0; nt < 8; nt++) {
        int col = ns*64 + nt*8 + 2*tig;
        float bb0 = bpr[col], bb1 = bpr[col+1];
        float* op0 = out + obase + (size_t)row0*DIM + col;
        float* op1 = out + obase + (size_t)row1*DIM + col;
        *(float2*)op0 = make_float2(oac[nt][0]*inv0 + acc2[nt][0]*dn0 + bb0,
                                    oac[nt][1]*inv0 + acc2[nt][1]*dn0 + bb1);
        *(float2*)op1 = make_float2(oac[nt][2]*inv1 + acc2[nt][2]*dn1 + bb0,
                                    oac[nt][3]*inv1 + acc2[nt][3]*dn1 + bb1);
    }
}

// ============================================================
extern "C" void kernel_launch(void* const* d_in, const int* in_sizes, int n_in,
                              void* d_out, int out_size) {
    const float* q = (const float*)d_in[0];
    const float* k = (const float*)d_in[1];
    const float* v = (const float*)d_in[2];
    const float* w = (const float*)d_in[3];
    const float* b = (const float*)d_in[4];
    float* out = (float*)d_out;

    int smKV = 2*128*KVS*2;                       // 69632
    int smKW = (32*KVS + 128*KVS)*2;              // 43520
    int smF  = STATS*2 + 448*4;                   // 114432
    cudaFuncSetAttribute(k_kvsum, cudaFuncAttributeMaxDynamicSharedMemorySize, smKV);
    cudaFuncSetAttribute(k_kvw,   cudaFuncAttributeMaxDynamicSharedMemorySize, smKW);
    cudaFuncSetAttribute(k_fused, cudaFuncAttributeMaxDynamicSharedMemorySize, smF);

    k_prep<<<BHN*NB, 256>>>((const float4*)q, (const float4*)k, (const float4*)v);
    k_topk<<<BHN, 1024>>>();
    k_kvsum<<<NCH*BHN, 256, smKV>>>(k);
    k_kvw<<<BHN*4, 256, smKW>>>((const float4*)w);
    k_fused<<<BHN*NB, 256, smF>>>(q, b, out);
}

// round 6
// speedup vs baseline: 6.0086x; 1.2449x over previous
#include <cuda_runtime.h>
#include <cuda_fp16.h>
#include <math.h>
#include <float.h>
#include <stdint.h>

#define BHN  32
#define LSEQ 2048
#define DIM  128
#define BLK  64
#define NB   32
#define TOP  4
#define NCH  16
#define CHL  (LSEQ/NCH)   // 128

// ---- scratch ----
__device__ __half g_qh[(size_t)BHN*LSEQ*DIM];   // fp16 q [bh][l][d]
__device__ __half g_kh[(size_t)BHN*LSEQ*DIM];   // fp16 k [bh][l][d]
__device__ __half g_vth[(size_t)BHN*DIM*LSEQ];  // fp16 v transposed [bh][d][l]
__device__ float  g_qb[BHN*NB*DIM];
__device__ float  g_kb[BHN*NB*DIM];
__device__ int    g_lut[BHN*NB*TOP];
__device__ float  g_ksum[BHN*DIM];
__device__ float  g_kv_part[(size_t)NCH*BHN*DIM*DIM];
__device__ float  g_ksum_part[NCH*BHN*DIM];
__device__ __half g_kvh[BHN*DIM*DIM];           // reduced kvsum, fp16
__device__ __half g_mt[BHN*DIM*DIM];            // (kv@W^T)^T : [bh][e2][d]

// ---- helpers ----
__device__ __forceinline__ uint32_t h2(float a, float b) {
    __half2 h = __floats2half2_rn(a, b);
    return *(uint32_t*)&h;
}
__device__ __forceinline__ void mma16(float* c,
        uint32_t a0, uint32_t a1, uint32_t a2, uint32_t a3,
        uint32_t b0, uint32_t b1) {
    asm volatile(
        "mma.sync.aligned.m16n8k16.row.col.f32.f16.f16.f32 "
        "{%0,%1,%2,%3},{%4,%5,%6,%7},{%8,%9},{%0,%1,%2,%3};\n"
        : "+f"(c[0]), "+f"(c[1]), "+f"(c[2]), "+f"(c[3])
        : "r"(a0), "r"(a1), "r"(a2), "r"(a3), "r"(b0), "r"(b1));
}
__device__ __forceinline__ uint32_t s2u(const void* p) {
    uint32_t a;
    asm("{ .reg .u64 t; cvta.to.shared.u64 t, %1; cvt.u32.u64 %0, t; }" : "=r"(a) : "l"(p));
    return a;
}
__device__ __forceinline__ void cpa16(uint32_t s, const void* g) {
    asm volatile("cp.async.cg.shared.global [%0],[%1],16;\n" :: "r"(s), "l"(g));
}
#define CP_COMMIT() asm volatile("cp.async.commit_group;\n")
#define CP_WAIT(n)  asm volatile("cp.async.wait_group " #n ";\n")

#define LDA4(PTR, STR) \
    a0 = *(const uint32_t*)(PTR); a1 = *(const uint32_t*)((PTR) + 8*(STR)); \
    a2 = *(const uint32_t*)((PTR) + 8); a3 = *(const uint32_t*)((PTR) + 8*(STR) + 8)
#define LDB2(PTR) \
    b0 = *(const uint32_t*)(PTR); b1 = *(const uint32_t*)((PTR) + 8)

// ============================================================
// K_prep: fp16 copies of q,k (natural) and v (transposed) + exact block means
// grid = BHN*NB = 1024, 256 threads
// ============================================================
__global__ void __launch_bounds__(256) k_prep(const float4* __restrict__ q4,
                                              const float4* __restrict__ k4,
                                              const float4* __restrict__ v4) {
    __shared__ float redq[8][132];
    __shared__ float redk[8][132];
    __shared__ __align__(16) __half sVn[64][136];   // natural [l][d], conflict-free
    int blk = blockIdx.x, tid = threadIdx.x;
    int c4 = tid & 31, rj = tid >> 5;
    size_t base = (size_t)blk * 64 * 32;
    uint2* qh2 = (uint2*)g_qh;
    uint2* kh2 = (uint2*)g_kh;

    float sq0=0,sq1=0,sq2=0,sq3=0, sk0=0,sk1=0,sk2=0,sk3=0;
#pragma unroll
    for (int i = 0; i < 8; i++) {
        int r = rj + 8*i;
        size_t off = base + (size_t)r*32 + c4;
        float4 a = q4[off];
        sq0+=a.x; sq1+=a.y; sq2+=a.z; sq3+=a.w;
        uint2 ua; ua.x = h2(a.x,a.y); ua.y = h2(a.z,a.w);
        qh2[off] = ua;
        float4 b = k4[off];
        sk0+=b.x; sk1+=b.y; sk2+=b.z; sk3+=b.w;
        uint2 ub; ub.x = h2(b.x,b.y); ub.y = h2(b.z,b.w);
        kh2[off] = ub;
        float4 c = v4[off];
        uint2 uv; uv.x = h2(c.x,c.y); uv.y = h2(c.z,c.w);
        *(uint2*)(&sVn[r][c4*4]) = uv;
    }
    redq[rj][c4*4+0]=sq0; redq[rj][c4*4+1]=sq1; redq[rj][c4*4+2]=sq2; redq[rj][c4*4+3]=sq3;
    redk[rj][c4*4+0]=sk0; redk[rj][c4*4+1]=sk1; redk[rj][c4*4+2]=sk2; redk[rj][c4*4+3]=sk3;
    __syncthreads();
    if (tid < DIM) {
        float s = 0.f, t = 0.f;
#pragma unroll
        for (int j = 0; j < 8; j++) { s += redq[j][tid]; t += redk[j][tid]; }
        g_qb[blk*DIM + tid] = s * (1.f/BLK);
        g_kb[blk*DIM + tid] = t * (1.f/BLK);
        // transpose V column d=tid in registers, write 64 halves (8 x uint4)
        int bh = blk >> 5, qb = blk & 31;
        uint32_t vv[32];
#pragma unroll
        for (int j = 0; j < 32; j++) {
            __half2 hp = __halves2half2(sVn[2*j][tid], sVn[2*j+1][tid]);
            vv[j] = *(uint32_t*)&hp;
        }
        uint4* dstr = (uint4*)(g_vth + ((size_t)(bh*DIM + tid))*LSEQ + qb*64);
#pragma unroll
        for (int j = 0; j < 8; j++)
            dstr[j] = make_uint4(vv[4*j], vv[4*j+1], vv[4*j+2], vv[4*j+3]);
    }
}

// ============================================================
// K2: blk_scores + top-4 (exact fp32, lowest-index tie-break)
// ============================================================
__global__ void k_topk() {
    __shared__ float sQ[NB][DIM];
    __shared__ float sK[NB][DIM+1];
    __shared__ float sS[NB][NB];
    int bh = blockIdx.x, tid = threadIdx.x;

    for (int i = tid; i < NB*DIM; i += 1024) {
        sQ[i>>7][i&127] = g_qb[bh*NB*DIM + i];
        sK[i>>7][i&127] = g_kb[bh*NB*DIM + i];
    }
    __syncthreads();
    {
        int qr = tid >> 5, kr = tid & 31;
        float acc = 0.f;
#pragma unroll 8
        for (int kk = 0; kk < DIM; kk++) acc += sQ[qr][kk] * sK[kr][kk];
        sS[qr][kr] = acc;
    }
    __syncthreads();

    int qr = tid >> 5, lane = tid & 31;
    float v = sS[qr][lane];
    int  mi = lane;
#pragma unroll
    for (int t = 0; t < TOP; t++) {
        float bv = v; int bi = mi;
#pragma unroll
        for (int off = 16; off; off >>= 1) {
            float ov = __shfl_xor_sync(0xffffffffu, bv, off);
            int   oi = __shfl_xor_sync(0xffffffffu, bi, off);
            if (ov > bv || (ov == bv && oi < bi)) { bv = ov; bi = oi; }
        }
        if (lane == 0) g_lut[(bh*NB + qr)*TOP + t] = bi;
        if (mi == bi) v = -FLT_MAX;
    }
}

// ============================================================
// K_kvsum: fused phi_k softmax (transposed into smem) + split-K phi^T@V
// grid = NCH*BHN = 512, 256 threads, fp16 mma
// ============================================================
#define KVS 136
__global__ void __launch_bounds__(256) k_kvsum(const float* __restrict__ kin) {
    extern __shared__ __half hsm[];
    __half* sPhiT = hsm;               // [128 d][136 l]
    __half* sVt   = hsm + 128*KVS;     // [128 e][136 l]

    int bid = blockIdx.x;
    int ch  = bid >> 5, bh = bid & 31;
    int tid = threadIdx.x, lane = tid & 31, warp = tid >> 5;
    int g = lane >> 2, tig = lane & 3;
    size_t lbase = (size_t)bh*LSEQ + (size_t)ch*CHL;

    {
        const __half* vp = g_vth + (size_t)bh*DIM*LSEQ + (size_t)ch*CHL;
#pragma unroll
        for (int i = 0; i < 8; i++) {
            int idx = tid + 256*i;
            int r = idx >> 4, c8 = (idx & 15)*8;
            cpa16(s2u(sVt + r*KVS + c8), vp + (size_t)r*LSEQ + c8);
        }
        CP_COMMIT();
    }

    for (int i = 0; i < 16; i++) {
        int r = warp*16 + i;
        const float* src = kin + (lbase + r)*DIM;
        float x0 = src[lane], x1 = src[lane+32], x2 = src[lane+64], x3 = src[lane+96];
        float m = fmaxf(fmaxf(x0,x1), fmaxf(x2,x3));
#pragma unroll
        for (int o = 16; o; o >>= 1) m = fmaxf(m, __shfl_xor_sync(0xffffffffu, m, o));
        float e0 = __expf(x0-m), e1 = __expf(x1-m), e2 = __expf(x2-m), e3 = __expf(x3-m);
        float s = e0+e1+e2+e3;
#pragma unroll
        for (int o = 16; o; o >>= 1) s += __shfl_xor_sync(0xffffffffu, s, o);
        float inv = 1.f/s;
        sPhiT[(lane)*KVS    + r] = __float2half_rn(e0*inv);
        sPhiT[(lane+32)*KVS + r] = __float2half_rn(e1*inv);
        sPhiT[(lane+64)*KVS + r] = __float2half_rn(e2*inv);
        sPhiT[(lane+96)*KVS + r] = __float2half_rn(e3*inv);
    }
    CP_WAIT(0);
    __syncthreads();

    if (tid < DIM) {
        const __half2* p = (const __half2*)(sPhiT + tid*KVS);
        float s = 0.f;
#pragma unroll 16
        for (int j = 0; j < 64; j++) { float2 f = __half22float2(p[j]); s += f.x + f.y; }
        g_ksum_part[bid*DIM + tid] = s;
    }

    float acc[16][4];
#pragma unroll
    for (int i = 0; i < 16; i++)
#pragma unroll
        for (int j = 0; j < 4; j++) acc[i][j] = 0.f;
    int m0 = warp*16;
    uint32_t a0,a1,a2,a3,b0,b1;
#pragma unroll
    for (int kk = 0; kk < 8; kk++) {
        int k0 = kk*16;
        const __half* ap = sPhiT + (m0+g)*KVS + k0 + 2*tig;
        LDA4(ap, KVS);
#pragma unroll
        for (int nt = 0; nt < 16; nt++) {
            const __half* bp = sVt + (nt*8+g)*KVS + k0 + 2*tig;
            LDB2(bp);
            mma16(acc[nt], a0,a1,a2,a3, b0,b1);
        }
    }
    float* dst = g_kv_part + (size_t)bid*DIM*DIM;
#pragma unroll
    for (int nt = 0; nt < 16; nt++) {
        int col = nt*8 + 2*tig;
        int row = m0 + g;
        *(float2*)&dst[row*DIM + col]     = make_float2(acc[nt][0], acc[nt][1]);
        *(float2*)&dst[(row+8)*DIM + col] = make_float2(acc[nt][2], acc[nt][3]);
    }
}

// ============================================================
// K_red: wide streaming reduction of split-K partials -> fp16 kv + ksum
// grid = 2048, 256 threads  (R2-style: 9us for 33.5MB)
// ============================================================
__global__ void k_red() {
    int idx = blockIdx.x*256 + threadIdx.x;     // BHN*DIM*DIM
    float s = 0.f;
#pragma unroll
    for (int ch = 0; ch < NCH; ch++) s += g_kv_part[(size_t)ch*BHN*DIM*DIM + idx];
    g_kvh[idx] = __float2half_rn(s);
    if (idx < BHN*DIM) {
        float t = 0.f;
#pragma unroll
        for (int ch = 0; ch < NCH; ch++) t += g_ksum_part[ch*BHN*DIM + idx];
        g_ksum[idx] = t;
    }
}

// ============================================================
// K_kvw: M^T = (kv @ W^T)^T fp16 — GEMM only
// grid = BHN*4 = 128, 256 threads; each block: 32 kv rows
// ============================================================
__global__ void __launch_bounds__(256) k_kvw(const float4* __restrict__ w4) {
    extern __shared__ __half hsm[];
    __half* sKV = hsm;              // [32 d][136 e]
    __half* sW  = hsm + 32*KVS;     // [128 e2][136 e]

    int bh = blockIdx.x >> 2, part = blockIdx.x & 3;
    int m0g = part*32;
    int tid = threadIdx.x, lane = tid & 31, warp = tid >> 5;
    int g = lane >> 2, tig = lane & 3;

    // load 32 kv rows (fp16, 8KB) vectorized
    for (int idx = tid; idx < 512; idx += 256) {
        int r = idx >> 4, c = (idx & 15)*8;
        *(uint4*)(sKV + r*KVS + c) =
            *(const uint4*)(g_kvh + (size_t)(bh*DIM + m0g + r)*DIM + c);
    }
    for (int i4 = tid; i4 < 4096; i4 += 256) {
        int e2 = i4 >> 5, ec = (i4 & 31)*4;
        float4 wv = w4[i4];
        *(uint32_t*)(sW + e2*KVS + ec)     = h2(wv.x, wv.y);
        *(uint32_t*)(sW + e2*KVS + ec + 2) = h2(wv.z, wv.w);
    }
    __syncthreads();

    int mt = warp & 1, ng = warp >> 1;
    int m0 = mt*16;
    float acc[4][4];
#pragma unroll
    for (int i = 0; i < 4; i++)
#pragma unroll
        for (int j = 0; j < 4; j++) acc[i][j] = 0.f;
    uint32_t a0,a1,a2,a3,b0,b1;
#pragma unroll
    for (int kk = 0; kk < 8; kk++) {
        int k0 = kk*16;
        const __half* ap = sKV + (m0+g)*KVS + k0 + 2*tig;
        LDA4(ap, KVS);
#pragma unroll
        for (int nt = 0; nt < 4; nt++) {
            const __half* bp = sW + (ng*32 + nt*8 + g)*KVS + k0 + 2*tig;
            LDB2(bp);
            mma16(acc[nt], a0,a1,a2,a3, b0,b1);
        }
    }
    __half* dst = g_mt + (size_t)bh*DIM*DIM;
    int row = m0g + m0 + g;
#pragma unroll
    for (int nt = 0; nt < 4; nt++) {
        int col = ng*32 + nt*8 + 2*tig;
        dst[col*DIM + row]         = __float2half_rn(acc[nt][0]);
        dst[(col+1)*DIM + row]     = __float2half_rn(acc[nt][1]);
        dst[col*DIM + row + 8]     = __float2half_rn(acc[nt][2]);
        dst[(col+1)*DIM + row + 8] = __float2half_rn(acc[nt][3]);
    }
}

// ============================================================
// K_fused: sparse attention (regs softmax) + linear half, fp16 mma
// grid = BHN*NB = 1024, 256 threads, 114432B smem -> 2 blocks/SM
// ============================================================
#define B0 8704
#define B1 18944
#define B2 29184
#define SPO 39424
#define PST2 264
#define STATS 56320
#define VSTR 80

__global__ void __launch_bounds__(256,2) k_fused(const float* __restrict__ q,
                                                 const float* __restrict__ bpr,
                                                 float* __restrict__ out) {
    extern __shared__ __half hsm[];
    __half* sQ = hsm;
    __half* sP = hsm + SPO;
    float* swmax = (float*)(hsm + STATS);   // [64][2]
    float* swsum = swmax + 128;             // [64][2]
    float* sks   = swsum + 128;             // [128]
    float* sden  = sks + 128;               // [64]

    int bid = blockIdx.x, bh = bid >> 5, qb = bid & 31;
    int tid = threadIdx.x, lane = tid & 31, warp = tid >> 5;
    int g = lane >> 2, tig = lane & 3;
    int mt = warp & 3, ns = warp >> 2;

    int lut[4];
#pragma unroll
    for (int t = 0; t < TOP; t++) lut[t] = g_lut[bid*TOP + t];
    if (tid < DIM) sks[tid] = g_ksum[bh*DIM + tid];

#define ISSUE64(SRC, DST) do {                                          \
        const __half* s_ = (SRC);                                       \
        _Pragma("unroll")                                               \
        for (int i_ = 0; i_ < 4; i_++) {                                \
            int idx_ = tid + 256*i_;                                    \
            int r_ = idx_ >> 4, c_ = (idx_ & 15)*8;                     \
            cpa16(s2u((DST) + r_*136 + c_), s_ + r_*128 + c_);          \
        }                                                               \
    } while (0)
#define ISSUE_VT(T, DST) do {                                           \
        const __half* s_ = g_vth + (size_t)bh*DIM*LSEQ + lut[T]*64;     \
        _Pragma("unroll")                                               \
        for (int i_ = 0; i_ < 4; i_++) {                                \
            int idx_ = tid + 256*i_;                                    \
            int r_ = idx_ >> 3, c_ = (idx_ & 7)*8;                      \
            cpa16(s2u((DST) + r_*VSTR + c_), s_ + (size_t)r_*LSEQ + c_);\
        }                                                               \
    } while (0)

    size_t qh_base = ((size_t)bh*LSEQ + (size_t)qb*BLK)*DIM;
    ISSUE64(g_qh + qh_base, sQ);
    ISSUE64(g_kh + ((size_t)bh*LSEQ + lut[0]*BLK)*DIM, hsm + B0);
    CP_COMMIT();
    ISSUE64(g_kh + ((size_t)bh*LSEQ + lut[1]*BLK)*DIM, hsm + B1);
    CP_COMMIT();
    ISSUE64(g_kh + ((size_t)bh*LSEQ + lut[2]*BLK)*DIM, hsm + B2);
    CP_COMMIT();

    float accS[4][4][4];
#pragma unroll
    for (int t = 0; t < 4; t++)
#pragma unroll
        for (int i = 0; i < 4; i++)
#pragma unroll
            for (int j = 0; j < 4; j++) accS[t][i][j] = 0.f;

    uint32_t a0,a1,a2,a3,b0,b1;

#define MMA_S(T, KB) do {                                               \
        _Pragma("unroll")                                               \
        for (int kk = 0; kk < 8; kk++) {                                \
            int k0 = kk*16;                                             \
            const __half* ap = sQ + (mt*16+g)*136 + k0 + 2*tig;         \
            LDA4(ap, 136);                                              \
            _Pragma("unroll")                                           \
            for (int nt = 0; nt < 4; nt++) {                            \
                const __half* bp = (KB) + (ns*32+nt*8+g)*136 + k0 + 2*tig; \
                LDB2(bp);                                               \
                mma16(accS[T][nt], a0,a1,a2,a3, b0,b1);                 \
            }                                                           \
        }                                                               \
    } while (0)

    CP_WAIT(2); __syncthreads();
    MMA_S(0, hsm + B0); __syncthreads();
    ISSUE64(g_kh + ((size_t)bh*LSEQ + lut[3]*BLK)*DIM, hsm + B0); CP_COMMIT();
    CP_WAIT(2); __syncthreads();
    MMA_S(1, hsm + B1); __syncthreads();
    ISSUE_VT(0, hsm + B1); CP_COMMIT();
    CP_WAIT(2); __syncthreads();
    MMA_S(2, hsm + B2); __syncthreads();
    ISSUE_VT(1, hsm + B2); CP_COMMIT();
    CP_WAIT(2); __syncthreads();
    MMA_S(3, hsm + B0); __syncthreads();
    ISSUE_VT(2, hsm + B0); CP_COMMIT();

    // ---- softmax over registers with cross-warp stats ----
    const float scale = 0.08838834764831845f;
    int row0 = mt*16 + g, row1 = row0 + 8;
    {
        float m0v = -FLT_MAX, m1v = -FLT_MAX;
#pragma unroll
        for (int t = 0; t < 4; t++)
#pragma unroll
            for (int nt = 0; nt < 4; nt++) {
                m0v = fmaxf(m0v, fmaxf(accS[t][nt][0], accS[t][nt][1]));
                m1v = fmaxf(m1v, fmaxf(accS[t][nt][2], accS[t][nt][3]));
            }
        m0v = fmaxf(m0v, __shfl_xor_sync(0xffffffffu, m0v, 1));
        m0v = fmaxf(m0v, __shfl_xor_sync(0xffffffffu, m0v, 2));
        m1v = fmaxf(m1v, __shfl_xor_sync(0xffffffffu, m1v, 1));
        m1v = fmaxf(m1v, __shfl_xor_sync(0xffffffffu, m1v, 2));
        if (tig == 0) { swmax[row0*2+ns] = m0v; swmax[row1*2+ns] = m1v; }
    }
    __syncthreads();
    {
        float gm0 = fmaxf(swmax[row0*2], swmax[row0*2+1]);
        float gm1 = fmaxf(swmax[row1*2], swmax[row1*2+1]);
        float s0 = 0.f, s1 = 0.f;
#pragma unroll
        for (int t = 0; t < 4; t++)
#pragma unroll
            for (int nt = 0; nt < 4; nt++) {
                float e0 = __expf((accS[t][nt][0]-gm0)*scale);
                float e1 = __expf((accS[t][nt][1]-gm0)*scale);
                float e2 = __expf((accS[t][nt][2]-gm1)*scale);
                float e3 = __expf((accS[t][nt][3]-gm1)*scale);
                s0 += e0 + e1; s1 += e2 + e3;
                int col = t*64 + ns*32 + nt*8 + 2*tig;
                *(uint32_t*)(sP + row0*PST2 + col) = h2(e0, e1);
                *(uint32_t*)(sP + row1*PST2 + col) = h2(e2, e3);
            }
        s0 += __shfl_xor_sync(0xffffffffu, s0, 1);
        s0 += __shfl_xor_sync(0xffffffffu, s0, 2);
        s1 += __shfl_xor_sync(0xffffffffu, s1, 1);
        s1 += __shfl_xor_sync(0xffffffffu, s1, 2);
        if (tig == 0) { swsum[row0*2+ns] = s0; swsum[row1*2+ns] = s1; }
    }

    // ---- PV ----
    float oac[8][4];
#pragma unroll
    for (int i = 0; i < 8; i++)
#pragma unroll
        for (int j = 0; j < 4; j++) oac[i][j] = 0.f;

#define MMA_PV(T, VB) do {                                              \
        _Pragma("unroll")                                               \
        for (int kk = 0; kk < 4; kk++) {                                \
            const __half* ap = sP + (mt*16+g)*PST2 + (T)*64 + kk*16 + 2*tig; \
            LDA4(ap, PST2);                                             \
            _Pragma("unroll")                                           \
            for (int nt = 0; nt < 8; nt++) {                            \
                const __half* bp = (VB) + (ns*64+nt*8+g)*VSTR + kk*16 + 2*tig; \
                LDB2(bp);                                               \
                mma16(oac[nt], a0,a1,a2,a3, b0,b1);                     \
            }                                                           \
        }                                                               \
    } while (0)

    CP_WAIT(2); __syncthreads();
    MMA_PV(0, hsm + B1); __syncthreads();
    ISSUE_VT(3, hsm + B1); CP_COMMIT();
    CP_WAIT(2); __syncthreads();
    MMA_PV(1, hsm + B2); __syncthreads();
    CP_WAIT(1); __syncthreads();
    MMA_PV(2, hsm + B0);
    __syncthreads();   // B0/sQ region dead across ALL warps before Mt overwrite
    {
        const __half* s_ = g_mt + (size_t)bh*DIM*DIM;
#pragma unroll
        for (int i_ = 0; i_ < 8; i_++) {
            int idx_ = tid + 256*i_;
            int r_ = idx_ >> 4, c_ = (idx_ & 15)*8;
            cpa16(s2u(hsm + r_*136 + c_), s_ + r_*128 + c_);
        }
        CP_COMMIT();
    }
    CP_WAIT(1); __syncthreads();
    MMA_PV(3, hsm + B1);

    // ---- phi_q (exact) into B2 + den ----
    for (int r = warp; r < BLK; r += 8) {
        const float* src = q + ((size_t)bh*LSEQ + (size_t)qb*BLK + r)*DIM;
        float x0 = src[lane], x1 = src[lane+32], x2 = src[lane+64], x3 = src[lane+96];
        float m = fmaxf(fmaxf(x0,x1), fmaxf(x2,x3));
#pragma unroll
        for (int o = 16; o; o >>= 1) m = fmaxf(m, __shfl_xor_sync(0xffffffffu, m, o));
        float e0 = __expf(x0-m), e1 = __expf(x1-m), e2 = __expf(x2-m), e3 = __expf(x3-m);
        float s = e0+e1+e2+e3;
#pragma unroll
        for (int o = 16; o; o >>= 1) s += __shfl_xor_sync(0xffffffffu, s, o);
        float inv = 1.f/s;
        e0 *= inv; e1 *= inv; e2 *= inv; e3 *= inv;
        float dp = e0*sks[lane] + e1*sks[lane+32] + e2*sks[lane+64] + e3*sks[lane+96];
#pragma unroll
        for (int o = 16; o; o >>= 1) dp += __shfl_xor_sync(0xffffffffu, dp, o);
        __half* dst = hsm + B2 + r*136;
        dst[lane]    = __float2half_rn(e0);
        dst[lane+32] = __float2half_rn(e1);
        dst[lane+64] = __float2half_rn(e2);
        dst[lane+96] = __float2half_rn(e3);
        if (lane == 0) sden[r] = 1.f/(1e-5f + dp);
    }
    CP_WAIT(0);
    __syncthreads();

    // ---- linear GEMM: o_pre = phi_q @ M ----
    float acc2[8][4];
#pragma unroll
    for (int i = 0; i < 8; i++)
#pragma unroll
        for (int j = 0; j < 4; j++) acc2[i][j] = 0.f;
#pragma unroll
    for (int kk = 0; kk < 8; kk++) {
        int k0 = kk*16;
        const __half* ap = hsm + B2 + (mt*16+g)*136 + k0 + 2*tig;
        LDA4(ap, 136);
#pragma unroll
        for (int nt = 0; nt < 8; nt++) {
            const __half* bp = hsm + (ns*64+nt*8+g)*136 + k0 + 2*tig;
            LDB2(bp);
            mma16(acc2[nt], a0,a1,a2,a3, b0,b1);
        }
    }

    // ---- epilogue: out = o_s + o_l + bias ----
    float inv0 = 1.f/(swsum[row0*2] + swsum[row0*2+1]);
    float inv1 = 1.f/(swsum[row1*2] + swsum[row1*2+1]);
    float dn0 = sden[row0], dn1 = sden[row1];
    size_t obase = ((size_t)bh*LSEQ + (size_t)qb*BLK)*DIM;
#pragma unroll
    for (int nt = 0; nt < 8; nt++) {
        int col = ns*64 + nt*8 + 2*tig;
        float bb0 = bpr[col], bb1 = bpr[col+1];
        float* op0 = out + obase + (size_t)row0*DIM + col;
        float* op1 = out + obase + (size_t)row1*DIM + col;
        *(float2*)op0 = make_float2(oac[nt][0]*inv0 + acc2[nt][0]*dn0 + bb0,
                                    oac[nt][1]*inv0 + acc2[nt][1]*dn0 + bb1);
        *(float2*)op1 = make_float2(oac[nt][2]*inv1 + acc2[nt][2]*dn1 + bb0,
                                    oac[nt][3]*inv1 + acc2[nt][3]*dn1 + bb1);
    }
}

// ============================================================
extern "C" void kernel_launch(void* const* d_in, const int* in_sizes, int n_in,
                              void* d_out, int out_size) {
    const float* q = (const float*)d_in[0];
    const float* k = (const float*)d_in[1];
    const float* v = (const float*)d_in[2];
    const float* w = (const float*)d_in[3];
    const float* b = (const float*)d_in[4];
    float* out = (float*)d_out;

    int smKV = 2*128*KVS*2;                       // 69632
    int smKW = (32*KVS + 128*KVS)*2;              // 43520
    int smF  = STATS*2 + 448*4;                   // 114432
    cudaFuncSetAttribute(k_kvsum, cudaFuncAttributeMaxDynamicSharedMemorySize, smKV);
    cudaFuncSetAttribute(k_kvw,   cudaFuncAttributeMaxDynamicSharedMemorySize, smKW);
    cudaFuncSetAttribute(k_fused, cudaFuncAttributeMaxDynamicSharedMemorySize, smF);

    k_prep<<<BHN*NB, 256>>>((const float4*)q, (const float4*)k, (const float4*)v);
    k_topk<<<BHN, 1024>>>();
    k_kvsum<<<NCH*BHN, 256, smKV>>>(k);
    k_red<<<(BHN*DIM*DIM)/256, 256>>>();
    k_kvw<<<BHN*4, 256, smKW>>>((const float4*)w);
    k_fused<<<BHN*NB, 256, smF>>>(q, b, out);
}

// round 7
// speedup vs baseline: 6.5188x; 1.0849x over previous
#include <cuda_runtime.h>
#include <cuda_fp16.h>
#include <math.h>
#include <float.h>
#include <stdint.h>

#define BHN  32
#define LSEQ 2048
#define DIM  128
#define BLK  64
#define NB   32
#define TOP  4
#define NCH  16
#define CHL  (LSEQ/NCH)   // 128

// ---- scratch ----
__device__ __half g_qh[(size_t)BHN*LSEQ*DIM];    // fp16 q [bh][l][d]
__device__ __half g_kh[(size_t)BHN*LSEQ*DIM];    // fp16 k [bh][l][d]
__device__ __half g_vth[(size_t)BHN*DIM*LSEQ];   // fp16 v^T [bh][d][l]
__device__ __half g_phiqh[(size_t)BHN*LSEQ*DIM]; // fp16 phi_q [bh][l][d]
__device__ __half g_phikt[(size_t)BHN*DIM*LSEQ]; // fp16 phi_k^T [bh][d][l]
__device__ float  g_qb[BHN*NB*DIM];
__device__ float  g_kb[BHN*NB*DIM];
__device__ int    g_lut[BHN*NB*TOP];
__device__ float  g_ksum[BHN*DIM];
__device__ float  g_kv_part[(size_t)NCH*BHN*DIM*DIM];
__device__ float  g_ksum_part[NCH*BHN*DIM];
__device__ __half g_kvh[BHN*DIM*DIM];            // reduced kvsum, fp16
__device__ __half g_mt[BHN*DIM*DIM];             // (kv@W^T)^T : [bh][e2][d]

// ---- helpers ----
__device__ __forceinline__ uint32_t h2(float a, float b) {
    __half2 h = __floats2half2_rn(a, b);
    return *(uint32_t*)&h;
}
__device__ __forceinline__ void mma16(float* c,
        uint32_t a0, uint32_t a1, uint32_t a2, uint32_t a3,
        uint32_t b0, uint32_t b1) {
    asm volatile(
        "mma.sync.aligned.m16n8k16.row.col.f32.f16.f16.f32 "
        "{%0,%1,%2,%3},{%4,%5,%6,%7},{%8,%9},{%0,%1,%2,%3};\n"
        : "+f"(c[0]), "+f"(c[1]), "+f"(c[2]), "+f"(c[3])
        : "r"(a0), "r"(a1), "r"(a2), "r"(a3), "r"(b0), "r"(b1));
}
__device__ __forceinline__ uint32_t s2u(const void* p) {
    uint32_t a;
    asm("{ .reg .u64 t; cvta.to.shared.u64 t, %1; cvt.u32.u64 %0, t; }" : "=r"(a) : "l"(p));
    return a;
}
__device__ __forceinline__ void cpa16(uint32_t s, const void* g) {
    asm volatile("cp.async.cg.shared.global [%0],[%1],16;\n" :: "r"(s), "l"(g));
}
#define CP_COMMIT() asm volatile("cp.async.commit_group;\n")
#define CP_WAIT(n)  asm volatile("cp.async.wait_group " #n ";\n")

#define LDA4(PTR, STR) \
    a0 = *(const uint32_t*)(PTR); a1 = *(const uint32_t*)((PTR) + 8*(STR)); \
    a2 = *(const uint32_t*)((PTR) + 8); a3 = *(const uint32_t*)((PTR) + 8*(STR) + 8)
#define LDB2(PTR) \
    b0 = *(const uint32_t*)(PTR); b1 = *(const uint32_t*)((PTR) + 8)

// warp-wide row softmax on 4 register values (all 32 lanes hold the same row)
#define ROW_SOFTMAX(X0,X1,X2,X3, E0,E1,E2,E3)  do {                     \
        float mx_ = fmaxf(fmaxf(X0,X1), fmaxf(X2,X3));                  \
        _Pragma("unroll")                                               \
        for (int o_ = 16; o_; o_ >>= 1)                                 \
            mx_ = fmaxf(mx_, __shfl_xor_sync(0xffffffffu, mx_, o_));    \
        E0 = __expf(X0-mx_); E1 = __expf(X1-mx_);                       \
        E2 = __expf(X2-mx_); E3 = __expf(X3-mx_);                       \
        float s_ = E0+E1+E2+E3;                                         \
        _Pragma("unroll")                                               \
        for (int o_ = 16; o_; o_ >>= 1)                                 \
            s_ += __shfl_xor_sync(0xffffffffu, s_, o_);                 \
        float iv_ = 1.f/s_;                                             \
        E0 *= iv_; E1 *= iv_; E2 *= iv_; E3 *= iv_;                     \
    } while (0)

// ============================================================
// K_prep: fp16 q,k (natural), v^T, phi_q (natural), phi_k^T + block means
// grid = BHN*NB = 1024, 256 threads
// ============================================================
__global__ void __launch_bounds__(256) k_prep(const float4* __restrict__ q4,
                                              const float4* __restrict__ k4,
                                              const float4* __restrict__ v4) {
    __shared__ float redq[8][132];
    __shared__ float redk[8][132];
    __shared__ __align__(16) __half sVn[64][136];   // natural [l][d]
    __shared__ __align__(16) __half sPn[64][136];   // phi_k natural [l][d]
    int blk = blockIdx.x, tid = threadIdx.x;
    int c4 = tid & 31, rj = tid >> 5;
    size_t base = (size_t)blk * 64 * 32;
    uint2* qh2 = (uint2*)g_qh;
    uint2* kh2 = (uint2*)g_kh;
    uint2* pq2 = (uint2*)g_phiqh;

    float sq0=0,sq1=0,sq2=0,sq3=0, sk0=0,sk1=0,sk2=0,sk3=0;
#pragma unroll
    for (int i = 0; i < 8; i++) {
        int r = rj + 8*i;
        size_t off = base + (size_t)r*32 + c4;
        // ---- q: copy + phi_q ----
        float4 a = q4[off];
        sq0+=a.x; sq1+=a.y; sq2+=a.z; sq3+=a.w;
        uint2 ua; ua.x = h2(a.x,a.y); ua.y = h2(a.z,a.w);
        qh2[off] = ua;
        float e0,e1,e2,e3;
        ROW_SOFTMAX(a.x,a.y,a.z,a.w, e0,e1,e2,e3);
        uint2 up; up.x = h2(e0,e1); up.y = h2(e2,e3);
        pq2[off] = up;
        // ---- k: copy + phi_k (staged for transpose) ----
        float4 b = k4[off];
        sk0+=b.x; sk1+=b.y; sk2+=b.z; sk3+=b.w;
        uint2 ub; ub.x = h2(b.x,b.y); ub.y = h2(b.z,b.w);
        kh2[off] = ub;
        float f0,f1,f2,f3;
        ROW_SOFTMAX(b.x,b.y,b.z,b.w, f0,f1,f2,f3);
        uint2 uk; uk.x = h2(f0,f1); uk.y = h2(f2,f3);
        *(uint2*)(&sPn[r][c4*4]) = uk;
        // ---- v: staged for transpose ----
        float4 c = v4[off];
        uint2 uv; uv.x = h2(c.x,c.y); uv.y = h2(c.z,c.w);
        *(uint2*)(&sVn[r][c4*4]) = uv;
    }
    redq[rj][c4*4+0]=sq0; redq[rj][c4*4+1]=sq1; redq[rj][c4*4+2]=sq2; redq[rj][c4*4+3]=sq3;
    redk[rj][c4*4+0]=sk0; redk[rj][c4*4+1]=sk1; redk[rj][c4*4+2]=sk2; redk[rj][c4*4+3]=sk3;
    __syncthreads();
    if (tid < DIM) {
        float s = 0.f, t = 0.f;
#pragma unroll
        for (int j = 0; j < 8; j++) { s += redq[j][tid]; t += redk[j][tid]; }
        g_qb[blk*DIM + tid] = s * (1.f/BLK);
        g_kb[blk*DIM + tid] = t * (1.f/BLK);
        int bh = blk >> 5, qb = blk & 31;
        // transpose V column d=tid
        uint32_t vv[32];
#pragma unroll
        for (int j = 0; j < 32; j++) {
            __half2 hp = __halves2half2(sVn[2*j][tid], sVn[2*j+1][tid]);
            vv[j] = *(uint32_t*)&hp;
        }
        uint4* dstr = (uint4*)(g_vth + ((size_t)(bh*DIM + tid))*LSEQ + qb*64);
#pragma unroll
        for (int j = 0; j < 8; j++)
            dstr[j] = make_uint4(vv[4*j], vv[4*j+1], vv[4*j+2], vv[4*j+3]);
        // transpose phi_k column d=tid
#pragma unroll
        for (int j = 0; j < 32; j++) {
            __half2 hp = __halves2half2(sPn[2*j][tid], sPn[2*j+1][tid]);
            vv[j] = *(uint32_t*)&hp;
        }
        uint4* dstp = (uint4*)(g_phikt + ((size_t)(bh*DIM + tid))*LSEQ + qb*64);
#pragma unroll
        for (int j = 0; j < 8; j++)
            dstp[j] = make_uint4(vv[4*j], vv[4*j+1], vv[4*j+2], vv[4*j+3]);
    }
}

// ============================================================
// K2: blk_scores + top-4 (exact fp32, lowest-index tie-break)
// ============================================================
__global__ void k_topk() {
    __shared__ float sQ[NB][DIM];
    __shared__ float sK[NB][DIM+1];
    __shared__ float sS[NB][NB];
    int bh = blockIdx.x, tid = threadIdx.x;

    for (int i = tid; i < NB*DIM; i += 1024) {
        sQ[i>>7][i&127] = g_qb[bh*NB*DIM + i];
        sK[i>>7][i&127] = g_kb[bh*NB*DIM + i];
    }
    __syncthreads();
    {
        int qr = tid >> 5, kr = tid & 31;
        float acc = 0.f;
#pragma unroll 8
        for (int kk = 0; kk < DIM; kk++) acc += sQ[qr][kk] * sK[kr][kk];
        sS[qr][kr] = acc;
    }
    __syncthreads();

    int qr = tid >> 5, lane = tid & 31;
    float v = sS[qr][lane];
    int  mi = lane;
#pragma unroll
    for (int t = 0; t < TOP; t++) {
        float bv = v; int bi = mi;
#pragma unroll
        for (int off = 16; off; off >>= 1) {
            float ov = __shfl_xor_sync(0xffffffffu, bv, off);
            int   oi = __shfl_xor_sync(0xffffffffu, bi, off);
            if (ov > bv || (ov == bv && oi < bi)) { bv = ov; bi = oi; }
        }
        if (lane == 0) g_lut[(bh*NB + qr)*TOP + t] = bi;
        if (mi == bi) v = -FLT_MAX;
    }
}

// ============================================================
// K_kvsum: pure GEMM: kv_part = phiT @ V (both tiles via cp.async) + ksum part
// grid = NCH*BHN = 512, 256 threads
// ============================================================
#define KVS 136
__global__ void __launch_bounds__(256) k_kvsum() {
    extern __shared__ __half hsm[];
    __half* sPhiT = hsm;               // [128 d][136 l]
    __half* sVt   = hsm + 128*KVS;     // [128 e][136 l]

    int bid = blockIdx.x;
    int ch  = bid >> 5, bh = bid & 31;
    int tid = threadIdx.x, lane = tid & 31, warp = tid >> 5;
    int g = lane >> 2, tig = lane & 3;

    {
        const __half* pp = g_phikt + (size_t)bh*DIM*LSEQ + (size_t)ch*CHL;
        const __half* vp = g_vth   + (size_t)bh*DIM*LSEQ + (size_t)ch*CHL;
#pragma unroll
        for (int i = 0; i < 8; i++) {
            int idx = tid + 256*i;
            int r = idx >> 4, c8 = (idx & 15)*8;
            cpa16(s2u(sPhiT + r*KVS + c8), pp + (size_t)r*LSEQ + c8);
            cpa16(s2u(sVt   + r*KVS + c8), vp + (size_t)r*LSEQ + c8);
        }
        CP_COMMIT();
    }
    CP_WAIT(0);
    __syncthreads();

    if (tid < DIM) {
        const __half2* p = (const __half2*)(sPhiT + tid*KVS);
        float s = 0.f;
#pragma unroll 16
        for (int j = 0; j < 64; j++) { float2 f = __half22float2(p[j]); s += f.x + f.y; }
        g_ksum_part[bid*DIM + tid] = s;
    }

    float acc[16][4];
#pragma unroll
    for (int i = 0; i < 16; i++)
#pragma unroll
        for (int j = 0; j < 4; j++) acc[i][j] = 0.f;
    int m0 = warp*16;
    uint32_t a0,a1,a2,a3,b0,b1;
#pragma unroll
    for (int kk = 0; kk < 8; kk++) {
        int k0 = kk*16;
        const __half* ap = sPhiT + (m0+g)*KVS + k0 + 2*tig;
        LDA4(ap, KVS);
#pragma unroll
        for (int nt = 0; nt < 16; nt++) {
            const __half* bp = sVt + (nt*8+g)*KVS + k0 + 2*tig;
            LDB2(bp);
            mma16(acc[nt], a0,a1,a2,a3, b0,b1);
        }
    }
    float* dst = g_kv_part + (size_t)bid*DIM*DIM;
#pragma unroll
    for (int nt = 0; nt < 16; nt++) {
        int col = nt*8 + 2*tig;
        int row = m0 + g;
        *(float2*)&dst[row*DIM + col]     = make_float2(acc[nt][0], acc[nt][1]);
        *(float2*)&dst[(row+8)*DIM + col] = make_float2(acc[nt][2], acc[nt][3]);
    }
}

// ============================================================
// K_red: wide streaming reduction of split-K partials -> fp16 kv + ksum
// ============================================================
__global__ void k_red() {
    int idx = blockIdx.x*256 + threadIdx.x;
    float s = 0.f;
#pragma unroll
    for (int ch = 0; ch < NCH; ch++) s += g_kv_part[(size_t)ch*BHN*DIM*DIM + idx];
    g_kvh[idx] = __float2half_rn(s);
    if (idx < BHN*DIM) {
        float t = 0.f;
#pragma unroll
        for (int ch = 0; ch < NCH; ch++) t += g_ksum_part[ch*BHN*DIM + idx];
        g_ksum[idx] = t;
    }
}

// ============================================================
// K_kvw: M^T = (kv @ W^T)^T fp16 — GEMM only
// grid = BHN*4 = 128, 256 threads
// ============================================================
__global__ void __launch_bounds__(256) k_kvw(const float4* __restrict__ w4) {
    extern __shared__ __half hsm[];
    __half* sKV = hsm;              // [32 d][136 e]
    __half* sW  = hsm + 32*KVS;     // [128 e2][136 e]

    int bh = blockIdx.x >> 2, part = blockIdx.x & 3;
    int m0g = part*32;
    int tid = threadIdx.x, lane = tid & 31, warp = tid >> 5;
    int g = lane >> 2, tig = lane & 3;

    for (int idx = tid; idx < 512; idx += 256) {
        int r = idx >> 4, c = (idx & 15)*8;
        *(uint4*)(sKV + r*KVS + c) =
            *(const uint4*)(g_kvh + (size_t)(bh*DIM + m0g + r)*DIM + c);
    }
    for (int i4 = tid; i4 < 4096; i4 += 256) {
        int e2 = i4 >> 5, ec = (i4 & 31)*4;
        float4 wv = w4[i4];
        *(uint32_t*)(sW + e2*KVS + ec)     = h2(wv.x, wv.y);
        *(uint32_t*)(sW + e2*KVS + ec + 2) = h2(wv.z, wv.w);
    }
    __syncthreads();

    int mt = warp & 1, ng = warp >> 1;
    int m0 = mt*16;
    float acc[4][4];
#pragma unroll
    for (int i = 0; i < 4; i++)
#pragma unroll
        for (int j = 0; j < 4; j++) acc[i][j] = 0.f;
    uint32_t a0,a1,a2,a3,b0,b1;
#pragma unroll
    for (int kk = 0; kk < 8; kk++) {
        int k0 = kk*16;
        const __half* ap = sKV + (m0+g)*KVS + k0 + 2*tig;
        LDA4(ap, KVS);
#pragma unroll
        for (int nt = 0; nt < 4; nt++) {
            const __half* bp = sW + (ng*32 + nt*8 + g)*KVS + k0 + 2*tig;
            LDB2(bp);
            mma16(acc[nt], a0,a1,a2,a3, b0,b1);
        }
    }
    __half* dst = g_mt + (size_t)bh*DIM*DIM;
    int row = m0g + m0 + g;
#pragma unroll
    for (int nt = 0; nt < 4; nt++) {
        int col = ng*32 + nt*8 + 2*tig;
        dst[col*DIM + row]         = __float2half_rn(acc[nt][0]);
        dst[(col+1)*DIM + row]     = __float2half_rn(acc[nt][1]);
        dst[col*DIM + row + 8]     = __float2half_rn(acc[nt][2]);
        dst[(col+1)*DIM + row + 8] = __float2half_rn(acc[nt][3]);
    }
}

// ============================================================
// K_fused: sparse attention + linear half, fp16 mma
// grid = BHN*NB = 1024, 256 threads, 114432B smem -> 2 blocks/SM
// ============================================================
#define B0 8704
#define B1 18944
#define B2 29184
#define SPO 39424
#define PST2 264
#define STATS 56320
#define VSTR 80

__global__ void __launch_bounds__(256,2) k_fused(const float* __restrict__ bpr,
                                                 float* __restrict__ out) {
    extern __shared__ __half hsm[];
    __half* sQ = hsm;
    __half* sP = hsm + SPO;
    float* swmax = (float*)(hsm + STATS);   // [64][2]
    float* swsum = swmax + 128;             // [64][2]
    float* sks   = swsum + 128;             // [128]
    float* sden  = sks + 128;               // [64]

    int bid = blockIdx.x, bh = bid >> 5, qb = bid & 31;
    int tid = threadIdx.x, lane = tid & 31, warp = tid >> 5;
    int g = lane >> 2, tig = lane & 3;
    int mt = warp & 3, ns = warp >> 2;

    int lut[4];
#pragma unroll
    for (int t = 0; t < TOP; t++) lut[t] = g_lut[bid*TOP + t];
    if (tid < DIM) sks[tid] = g_ksum[bh*DIM + tid];

#define ISSUE64(SRC, DST) do {                                          \
        const __half* s_ = (SRC);                                       \
        _Pragma("unroll")                                               \
        for (int i_ = 0; i_ < 4; i_++) {                                \
            int idx_ = tid + 256*i_;                                    \
            int r_ = idx_ >> 4, c_ = (idx_ & 15)*8;                     \
            cpa16(s2u((DST) + r_*136 + c_), s_ + r_*128 + c_);          \
        }                                                               \
    } while (0)
#define ISSUE_VT(T, DST) do {                                           \
        const __half* s_ = g_vth + (size_t)bh*DIM*LSEQ + lut[T]*64;     \
        _Pragma("unroll")                                               \
        for (int i_ = 0; i_ < 4; i_++) {                                \
            int idx_ = tid + 256*i_;                                    \
            int r_ = idx_ >> 3, c_ = (idx_ & 7)*8;                      \
            cpa16(s2u((DST) + r_*VSTR + c_), s_ + (size_t)r_*LSEQ + c_);\
        }                                                               \
    } while (0)

    size_t qh_base = ((size_t)bh*LSEQ + (size_t)qb*BLK)*DIM;
    ISSUE64(g_qh + qh_base, sQ);
    ISSUE64(g_kh + ((size_t)bh*LSEQ + lut[0]*BLK)*DIM, hsm + B0);
    CP_COMMIT();                                                  // G1
    ISSUE64(g_kh + ((size_t)bh*LSEQ + lut[1]*BLK)*DIM, hsm + B1);
    CP_COMMIT();                                                  // G2
    ISSUE64(g_kh + ((size_t)bh*LSEQ + lut[2]*BLK)*DIM, hsm + B2);
    CP_COMMIT();                                                  // G3

    float accS[4][4][4];
#pragma unroll
    for (int t = 0; t < 4; t++)
#pragma unroll
        for (int i = 0; i < 4; i++)
#pragma unroll
            for (int j = 0; j < 4; j++) accS[t][i][j] = 0.f;

    uint32_t a0,a1,a2,a3,b0,b1;

#define MMA_S(T, KB) do {                                               \
        _Pragma("unroll")                                               \
        for (int kk = 0; kk < 8; kk++) {                                \
            int k0 = kk*16;                                             \
            const __half* ap = sQ + (mt*16+g)*136 + k0 + 2*tig;         \
            LDA4(ap, 136);                                              \
            _Pragma("unroll")                                           \
            for (int nt = 0; nt < 4; nt++) {                            \
                const __half* bp = (KB) + (ns*32+nt*8+g)*136 + k0 + 2*tig; \
                LDB2(bp);                                               \
                mma16(accS[T][nt], a0,a1,a2,a3, b0,b1);                 \
            }                                                           \
        }                                                               \
    } while (0)

    CP_WAIT(2); __syncthreads();
    MMA_S(0, hsm + B0); __syncthreads();
    ISSUE64(g_kh + ((size_t)bh*LSEQ + lut[3]*BLK)*DIM, hsm + B0); CP_COMMIT();  // G4
    CP_WAIT(2); __syncthreads();
    MMA_S(1, hsm + B1); __syncthreads();
    ISSUE_VT(0, hsm + B1); CP_COMMIT();                                          // G5
    CP_WAIT(2); __syncthreads();
    MMA_S(2, hsm + B2); __syncthreads();
    ISSUE_VT(1, hsm + B2); CP_COMMIT();                                          // G6
    CP_WAIT(2); __syncthreads();
    MMA_S(3, hsm + B0); __syncthreads();
    ISSUE_VT(2, hsm + B0); CP_COMMIT();                                          // G7

    // ---- softmax over registers with cross-warp stats ----
    const float scale = 0.08838834764831845f;
    int row0 = mt*16 + g, row1 = row0 + 8;
    {
        float m0v = -FLT_MAX, m1v = -FLT_MAX;
#pragma unroll
        for (int t = 0; t < 4; t++)
#pragma unroll
            for (int nt = 0; nt < 4; nt++) {
                m0v = fmaxf(m0v, fmaxf(accS[t][nt][0], accS[t][nt][1]));
                m1v = fmaxf(m1v, fmaxf(accS[t][nt][2], accS[t][nt][3]));
            }
        m0v = fmaxf(m0v, __shfl_xor_sync(0xffffffffu, m0v, 1));
        m0v = fmaxf(m0v, __shfl_xor_sync(0xffffffffu, m0v, 2));
        m1v = fmaxf(m1v, __shfl_xor_sync(0xffffffffu, m1v, 1));
        m1v = fmaxf(m1v, __shfl_xor_sync(0xffffffffu, m1v, 2));
        if (tig == 0) { swmax[row0*2+ns] = m0v; swmax[row1*2+ns] = m1v; }
    }
    __syncthreads();
    {
        float gm0 = fmaxf(swmax[row0*2], swmax[row0*2+1]);
        float gm1 = fmaxf(swmax[row1*2], swmax[row1*2+1]);
        float s0 = 0.f, s1 = 0.f;
#pragma unroll
        for (int t = 0; t < 4; t++)
#pragma unroll
            for (int nt = 0; nt < 4; nt++) {
                float e0 = __expf((accS[t][nt][0]-gm0)*scale);
                float e1 = __expf((accS[t][nt][1]-gm0)*scale);
                float e2 = __expf((accS[t][nt][2]-gm1)*scale);
                float e3 = __expf((accS[t][nt][3]-gm1)*scale);
                s0 += e0 + e1; s1 += e2 + e3;
                int col = t*64 + ns*32 + nt*8 + 2*tig;
                *(uint32_t*)(sP + row0*PST2 + col) = h2(e0, e1);
                *(uint32_t*)(sP + row1*PST2 + col) = h2(e2, e3);
            }
        s0 += __shfl_xor_sync(0xffffffffu, s0, 1);
        s0 += __shfl_xor_sync(0xffffffffu, s0, 2);
        s1 += __shfl_xor_sync(0xffffffffu, s1, 1);
        s1 += __shfl_xor_sync(0xffffffffu, s1, 2);
        if (tig == 0) { swsum[row0*2+ns] = s0; swsum[row1*2+ns] = s1; }
    }

    // ---- PV ----
    float oac[8][4];
#pragma unroll
    for (int i = 0; i < 8; i++)
#pragma unroll
        for (int j = 0; j < 4; j++) oac[i][j] = 0.f;

#define MMA_PV(T, VB) do {                                              \
        _Pragma("unroll")                                               \
        for (int kk = 0; kk < 4; kk++) {                                \
            const __half* ap = sP + (mt*16+g)*PST2 + (T)*64 + kk*16 + 2*tig; \
            LDA4(ap, PST2);                                             \
            _Pragma("unroll")                                           \
            for (int nt = 0; nt < 8; nt++) {                            \
                const __half* bp = (VB) + (ns*64+nt*8+g)*VSTR + kk*16 + 2*tig; \
                LDB2(bp);                                               \
                mma16(oac[nt], a0,a1,a2,a3, b0,b1);                     \
            }                                                           \
        }                                                               \
    } while (0)

    CP_WAIT(2); __syncthreads();            // V0 ready
    MMA_PV(0, hsm + B1); __syncthreads();
    ISSUE_VT(3, hsm + B1); CP_COMMIT();                                          // G8
    CP_WAIT(2); __syncthreads();            // V1 ready
    MMA_PV(1, hsm + B2);
    __syncthreads();                        // all warps done reading B2
    ISSUE64(g_phiqh + qh_base, hsm + B2); CP_COMMIT();                           // G9
    CP_WAIT(2); __syncthreads();            // V2 ready (G7)
    MMA_PV(2, hsm + B0);
    __syncthreads();                        // base/sQ + B0 dead across all warps
    {
        const __half* s_ = g_mt + (size_t)bh*DIM*DIM;
#pragma unroll
        for (int i_ = 0; i_ < 8; i_++) {
            int idx_ = tid + 256*i_;
            int r_ = idx_ >> 4, c_ = (idx_ & 15)*8;
            cpa16(s2u(hsm + r_*136 + c_), s_ + r_*128 + c_);
        }
        CP_COMMIT();                                                             // G10
    }
    CP_WAIT(2); __syncthreads();            // V3 ready (G8)
    MMA_PV(3, hsm + B1);

    // ---- den = phi_q . ksum (phi_q fp16 in B2) ----
    CP_WAIT(1); __syncthreads();            // phi_q ready (G9)
    for (int r = warp; r < BLK; r += 8) {
        const __half* pr = hsm + B2 + r*136;
        float dp = __half2float(pr[lane])    * sks[lane]
                 + __half2float(pr[lane+32]) * sks[lane+32]
                 + __half2float(pr[lane+64]) * sks[lane+64]
                 + __half2float(pr[lane+96]) * sks[lane+96];
#pragma unroll
        for (int o = 16; o; o >>= 1) dp += __shfl_xor_sync(0xffffffffu, dp, o);
        if (lane == 0) sden[r] = 1.f/(1e-5f + dp);
    }
    CP_WAIT(0);                             // Mt ready (G10)
    __syncthreads();

    // ---- linear GEMM: o_pre = phi_q @ M ----
    float acc2[8][4];
#pragma unroll
    for (int i = 0; i < 8; i++)
#pragma unroll
        for (int j = 0; j < 4; j++) acc2[i][j] = 0.f;
#pragma unroll
    for (int kk = 0; kk < 8; kk++) {
        int k0 = kk*16;
        const __half* ap = hsm + B2 + (mt*16+g)*136 + k0 + 2*tig;
        LDA4(ap, 136);
#pragma unroll
        for (int nt = 0; nt < 8; nt++) {
            const __half* bp = hsm + (ns*64+nt*8+g)*136 + k0 + 2*tig;
            LDB2(bp);
            mma16(acc2[nt], a0,a1,a2,a3, b0,b1);
        }
    }

    // ---- epilogue: out = o_s + o_l + bias ----
    float inv0 = 1.f/(swsum[row0*2] + swsum[row0*2+1]);
    float inv1 = 1.f/(swsum[row1*2] + swsum[row1*2+1]);
    float dn0 = sden[row0], dn1 = sden[row1];
    size_t obase = ((size_t)bh*LSEQ + (size_t)qb*BLK)*DIM;
#pragma unroll
    for (int nt = 0; nt < 8; nt++) {
        int col = ns*64 + nt*8 + 2*tig;
        float bb0 = bpr[col], bb1 = bpr[col+1];
        float* op0 = out + obase + (size_t)row0*DIM + col;
        float* op1 = out + obase + (size_t)row1*DIM + col;
        *(float2*)op0 = make_float2(oac[nt][0]*inv0 + acc2[nt][0]*dn0 + bb0,
                                    oac[nt][1]*inv0 + acc2[nt][1]*dn0 + bb1);
        *(float2*)op1 = make_float2(oac[nt][2]*inv1 + acc2[nt][2]*dn1 + bb0,
                                    oac[nt][3]*inv1 + acc2[nt][3]*dn1 + bb1);
    }
}

// ============================================================
extern "C" void kernel_launch(void* const* d_in, const int* in_sizes, int n_in,
                              void* d_out, int out_size) {
    const float* q = (const float*)d_in[0];
    const float* k = (const float*)d_in[1];
    const float* v = (const float*)d_in[2];
    const float* w = (const float*)d_in[3];
    const float* b = (const float*)d_in[4];
    float* out = (float*)d_out;

    int smKV = 2*128*KVS*2;                       // 69632
    int smKW = (32*KVS + 128*KVS)*2;              // 43520
    int smF  = STATS*2 + 448*4;                   // 114432
    cudaFuncSetAttribute(k_kvsum, cudaFuncAttributeMaxDynamicSharedMemorySize, smKV);
    cudaFuncSetAttribute(k_kvw,   cudaFuncAttributeMaxDynamicSharedMemorySize, smKW);
    cudaFuncSetAttribute(k_fused, cudaFuncAttributeMaxDynamicSharedMemorySize, smF);

    k_prep<<<BHN*NB, 256>>>((const float4*)q, (const float4*)k, (const float4*)v);
    k_topk<<<BHN, 1024>>>();
    k_kvsum<<<NCH*BHN, 256, smKV>>>();
    k_red<<<(BHN*DIM*DIM)/256, 256>>>();
    k_kvw<<<BHN*4, 256, smKW>>>((const float4*)w);
    k_fused<<<BHN*NB, 256, smF>>>(b, out);
}

// round 9
// speedup vs baseline: 7.2803x; 1.1168x over previous
#include <cuda_runtime.h>
#include <cuda_fp16.h>
#include <math.h>
#include <float.h>
#include <stdint.h>

#define BHN  32
#define LSEQ 2048
#define DIM  128
#define BLK  64
#define NB   32
#define TOP  4
#define NCH  8
#define CHL  (LSEQ/NCH)   // 256 (2 sub-chunks of 128)

// ---- scratch ----
__device__ __half g_qh[(size_t)BHN*LSEQ*DIM];    // fp16 q [bh][l][d]
__device__ __half g_kh[(size_t)BHN*LSEQ*DIM];    // fp16 k [bh][l][d]
__device__ __half g_vth[(size_t)BHN*DIM*LSEQ];   // fp16 v^T [bh][d][l]
__device__ __half g_phiqh[(size_t)BHN*LSEQ*DIM]; // fp16 phi_q [bh][l][d]
__device__ __half g_phikt[(size_t)BHN*DIM*LSEQ]; // fp16 phi_k^T [bh][d][l]
__device__ float  g_qb[BHN*NB*DIM];
__device__ float  g_kb[BHN*NB*DIM];
__device__ int    g_lut[BHN*NB*TOP];
__device__ float  g_ksum[BHN*DIM];
__device__ float  g_kv_part[(size_t)NCH*BHN*DIM*DIM];
__device__ float  g_ksum_part[NCH*BHN*DIM];
__device__ __half g_kvh[BHN*DIM*DIM];            // reduced kvsum, fp16
__device__ __half g_mt[BHN*DIM*DIM];             // (kv@W^T)^T : [bh][e2][d]

// ---- helpers ----
__device__ __forceinline__ uint32_t h2(float a, float b) {
    __half2 h = __floats2half2_rn(a, b);
    return *(uint32_t*)&h;
}
__device__ __forceinline__ void mma16(float* c,
        uint32_t a0, uint32_t a1, uint32_t a2, uint32_t a3,
        uint32_t b0, uint32_t b1) {
    asm volatile(
        "mma.sync.aligned.m16n8k16.row.col.f32.f16.f16.f32 "
        "{%0,%1,%2,%3},{%4,%5,%6,%7},{%8,%9},{%0,%1,%2,%3};\n"
        : "+f"(c[0]), "+f"(c[1]), "+f"(c[2]), "+f"(c[3])
        : "r"(a0), "r"(a1), "r"(a2), "r"(a3), "r"(b0), "r"(b1));
}
__device__ __forceinline__ uint32_t s2u(const void* p) {
    uint32_t a;
    asm("{ .reg .u64 t; cvta.to.shared.u64 t, %1; cvt.u32.u64 %0, t; }" : "=r"(a) : "l"(p));
    return a;
}
__device__ __forceinline__ void cpa16(uint32_t s, const void* g) {
    asm volatile("cp.async.cg.shared.global [%0],[%1],16;\n" :: "r"(s), "l"(g));
}
#define CP_COMMIT() asm volatile("cp.async.commit_group;\n")
#define CP_WAIT(n)  asm volatile("cp.async.wait_group " #n ";\n")

__device__ __forceinline__ void ldsm4(uint32_t& r0, uint32_t& r1,
                                      uint32_t& r2, uint32_t& r3, uint32_t sa) {
    asm volatile("ldmatrix.sync.aligned.m8n8.x4.shared.b16 {%0,%1,%2,%3}, [%4];"
        : "=r"(r0), "=r"(r1), "=r"(r2), "=r"(r3) : "r"(sa));
}
// A-operand base (rows m0.., stride STR halves): lane row = (l&7)+((l>>3)&1)*8, col (l>>4)*8
#define A_ADDR(PTR, M0, STR) \
    (s2u(PTR) + (((M0) + (lane&7) + ((lane>>3)&1)*8)*(STR) + (lane>>4)*8)*2)
// B-pair base (rows n0.., 2 consecutive 8-col tiles): lane row = (l&7)+(l>>4)*8, col ((l>>3)&1)*8
#define B_ADDR(PTR, N0, STR) \
    (s2u(PTR) + (((N0) + (lane&7) + (lane>>4)*8)*(STR) + ((lane>>3)&1)*8)*2)

// warp-wide row softmax on 4 register values
#define ROW_SOFTMAX(X0,X1,X2,X3, E0,E1,E2,E3)  do {                     \
        float mx_ = fmaxf(fmaxf(X0,X1), fmaxf(X2,X3));                  \
        _Pragma("unroll")                                               \
        for (int o_ = 16; o_; o_ >>= 1)                                 \
            mx_ = fmaxf(mx_, __shfl_xor_sync(0xffffffffu, mx_, o_));    \
        E0 = __expf(X0-mx_); E1 = __expf(X1-mx_);                       \
        E2 = __expf(X2-mx_); E3 = __expf(X3-mx_);                       \
        float s_ = E0+E1+E2+E3;                                         \
        _Pragma("unroll")                                               \
        for (int o_ = 16; o_; o_ >>= 1)                                 \
            s_ += __shfl_xor_sync(0xffffffffu, s_, o_);                 \
        float iv_ = 1.f/s_;                                             \
        E0 *= iv_; E1 *= iv_; E2 *= iv_; E3 *= iv_;                     \
    } while (0)

// ============================================================
// K_prep
// ============================================================
__global__ void __launch_bounds__(256) k_prep(const float4* __restrict__ q4,
                                              const float4* __restrict__ k4,
                                              const float4* __restrict__ v4) {
    __shared__ float redq[8][132];
    __shared__ float redk[8][132];
    __shared__ __align__(16) __half sVn[64][136];
    __shared__ __align__(16) __half sPn[64][136];
    int blk = blockIdx.x, tid = threadIdx.x;
    int c4 = tid & 31, rj = tid >> 5;
    size_t base = (size_t)blk * 64 * 32;
    uint2* qh2 = (uint2*)g_qh;
    uint2* kh2 = (uint2*)g_kh;
    uint2* pq2 = (uint2*)g_phiqh;

    float sq0=0,sq1=0,sq2=0,sq3=0, sk0=0,sk1=0,sk2=0,sk3=0;
#pragma unroll
    for (int i = 0; i < 8; i++) {
        int r = rj + 8*i;
        size_t off = base + (size_t)r*32 + c4;
        float4 a = q4[off];
        sq0+=a.x; sq1+=a.y; sq2+=a.z; sq3+=a.w;
        uint2 ua; ua.x = h2(a.x,a.y); ua.y = h2(a.z,a.w);
        qh2[off] = ua;
        float e0,e1,e2,e3;
        ROW_SOFTMAX(a.x,a.y,a.z,a.w, e0,e1,e2,e3);
        uint2 up; up.x = h2(e0,e1); up.y = h2(e2,e3);
        pq2[off] = up;
        float4 b = k4[off];
        sk0+=b.x; sk1+=b.y; sk2+=b.z; sk3+=b.w;
        uint2 ub; ub.x = h2(b.x,b.y); ub.y = h2(b.z,b.w);
        kh2[off] = ub;
        float f0,f1,f2,f3;
        ROW_SOFTMAX(b.x,b.y,b.z,b.w, f0,f1,f2,f3);
        uint2 uk; uk.x = h2(f0,f1); uk.y = h2(f2,f3);
        *(uint2*)(&sPn[r][c4*4]) = uk;
        float4 c = v4[off];
        uint2 uv; uv.x = h2(c.x,c.y); uv.y = h2(c.z,c.w);
        *(uint2*)(&sVn[r][c4*4]) = uv;
    }
    redq[rj][c4*4+0]=sq0; redq[rj][c4*4+1]=sq1; redq[rj][c4*4+2]=sq2; redq[rj][c4*4+3]=sq3;
    redk[rj][c4*4+0]=sk0; redk[rj][c4*4+1]=sk1; redk[rj][c4*4+2]=sk2; redk[rj][c4*4+3]=sk3;
    __syncthreads();
    int bh = blk >> 5, qb = blk & 31;
    if (tid < DIM) {
        float s = 0.f, t = 0.f;
#pragma unroll
        for (int j = 0; j < 8; j++) { s += redq[j][tid]; t += redk[j][tid]; }
        g_qb[blk*DIM + tid] = s * (1.f/BLK);
        g_kb[blk*DIM + tid] = t * (1.f/BLK);
    }
    // split transposes: tid<128 -> V col d=tid ; tid>=128 -> phi_k col d=tid-128
    {
        int d = tid & 127;
        const __half (*srcm)[136] = (tid < 128) ? sVn : sPn;
        __half* gdst = (tid < 128) ? g_vth : g_phikt;
        uint32_t vv[32];
#pragma unroll
        for (int j = 0; j < 32; j++) {
            __half2 hp = __halves2half2(srcm[2*j][d], srcm[2*j+1][d]);
            vv[j] = *(uint32_t*)&hp;
        }
        uint4* dstr = (uint4*)(gdst + ((size_t)(bh*DIM + d))*LSEQ + qb*64);
#pragma unroll
        for (int j = 0; j < 8; j++)
            dstr[j] = make_uint4(vv[4*j], vv[4*j+1], vv[4*j+2], vv[4*j+3]);
    }
}

// ============================================================
// K2: blk_scores + top-4 (exact fp32, lowest-index tie-break)
// ============================================================
__global__ void k_topk() {
    __shared__ float sQ[NB][DIM];
    __shared__ float sK[NB][DIM+1];
    __shared__ float sS[NB][NB];
    int bh = blockIdx.x, tid = threadIdx.x;

    for (int i = tid; i < NB*DIM; i += 1024) {
        sQ[i>>7][i&127] = g_qb[bh*NB*DIM + i];
        sK[i>>7][i&127] = g_kb[bh*NB*DIM + i];
    }
    __syncthreads();
    {
        int qr = tid >> 5, kr = tid & 31;
        float acc = 0.f;
#pragma unroll 8
        for (int kk = 0; kk < DIM; kk++) acc += sQ[qr][kk] * sK[kr][kk];
        sS[qr][kr] = acc;
    }
    __syncthreads();

    int qr = tid >> 5, lane = tid & 31;
    float v = sS[qr][lane];
    int  mi = lane;
#pragma unroll
    for (int t = 0; t < TOP; t++) {
        float bv = v; int bi = mi;
#pragma unroll
        for (int off = 16; off; off >>= 1) {
            float ov = __shfl_xor_sync(0xffffffffu, bv, off);
            int   oi = __shfl_xor_sync(0xffffffffu, bi, off);
            if (ov > bv || (ov == bv && oi < bi)) { bv = ov; bi = oi; }
        }
        if (lane == 0) g_lut[(bh*NB + qr)*TOP + t] = bi;
        if (mi == bi) v = -FLT_MAX;
    }
}

// ============================================================
// K_kvsum: pure GEMM over 2x128-row chunks, ldmatrix, reg-accumulated
// grid = NCH*BHN = 256, 256 threads
// ============================================================
#define KVS 136
__global__ void __launch_bounds__(256) k_kvsum() {
    extern __shared__ __half hsm[];
    __half* sPhiT = hsm;               // [128 d][136 l]
    __half* sVt   = hsm + 128*KVS;     // [128 e][136 l]

    int bid = blockIdx.x;
    int ch  = bid >> 5, bh = bid & 31;
    int tid = threadIdx.x, lane = tid & 31, warp = tid >> 5;

    float acc[16][4];
#pragma unroll
    for (int i = 0; i < 16; i++)
#pragma unroll
        for (int j = 0; j < 4; j++) acc[i][j] = 0.f;
    float ks = 0.f;   // thread-private; tid<128 meaningful
    int m0 = warp*16;

    for (int sub = 0; sub < 2; sub++) {
        size_t loff = (size_t)ch*CHL + (size_t)sub*128;
        const __half* pp = g_phikt + (size_t)bh*DIM*LSEQ + loff;
        const __half* vp = g_vth   + (size_t)bh*DIM*LSEQ + loff;
#pragma unroll
        for (int i = 0; i < 8; i++) {
            int idx = tid + 256*i;
            int r = idx >> 4, c8 = (idx & 15)*8;
            cpa16(s2u(sPhiT + r*KVS + c8), pp + (size_t)r*LSEQ + c8);
            cpa16(s2u(sVt   + r*KVS + c8), vp + (size_t)r*LSEQ + c8);
        }
        CP_COMMIT();
        CP_WAIT(0);
        __syncthreads();

        if (tid < DIM) {
            const __half2* p = (const __half2*)(sPhiT + tid*KVS);
#pragma unroll 16
            for (int j = 0; j < 64; j++) { float2 f = __half22float2(p[j]); ks += f.x + f.y; }
        }

        uint32_t aB = A_ADDR(sPhiT, m0, KVS);
#pragma unroll
        for (int kk = 0; kk < 8; kk++) {
            int k0 = kk*16;
            uint32_t a0,a1,a2,a3;
            ldsm4(a0,a1,a2,a3, aB + k0*2);
#pragma unroll
            for (int np = 0; np < 8; np++) {
                uint32_t b00,b01,b10,b11;
                ldsm4(b00,b01,b10,b11, B_ADDR(sVt, np*16, KVS) + k0*2);
                mma16(acc[np*2],   a0,a1,a2,a3, b00,b01);
                mma16(acc[np*2+1], a0,a1,a2,a3, b10,b11);
            }
        }
        __syncthreads();
    }

    if (tid < DIM) g_ksum_part[bid*DIM + tid] = ks;

    int g = lane >> 2, tig = lane & 3;
    float* dst = g_kv_part + (size_t)bid*DIM*DIM;
#pragma unroll
    for (int nt = 0; nt < 16; nt++) {
        int col = nt*8 + 2*tig;
        int row = m0 + g;
        *(float2*)&dst[row*DIM + col]     = make_float2(acc[nt][0], acc[nt][1]);
        *(float2*)&dst[(row+8)*DIM + col] = make_float2(acc[nt][2], acc[nt][3]);
    }
}

// ============================================================
// K_red: wide streaming reduction of split-K partials
// ============================================================
__global__ void k_red() {
    int idx = blockIdx.x*256 + threadIdx.x;
    float s = 0.f;
#pragma unroll
    for (int ch = 0; ch < NCH; ch++) s += g_kv_part[(size_t)ch*BHN*DIM*DIM + idx];
    g_kvh[idx] = __float2half_rn(s);
    if (idx < BHN*DIM) {
        float t = 0.f;
#pragma unroll
        for (int ch = 0; ch < NCH; ch++) t += g_ksum_part[ch*BHN*DIM + idx];
        g_ksum[idx] = t;
    }
}

// ============================================================
// K_kvw: M^T = (kv @ W^T)^T fp16 — GEMM only
// ============================================================
__global__ void __launch_bounds__(256) k_kvw(const float4* __restrict__ w4) {
    extern __shared__ __half hsm[];
    __half* sKV = hsm;              // [32 d][136 e]
    __half* sW  = hsm + 32*KVS;     // [128 e2][136 e]

    int bh = blockIdx.x >> 2, part = blockIdx.x & 3;
    int m0g = part*32;
    int tid = threadIdx.x, lane = tid & 31, warp = tid >> 5;

    for (int idx = tid; idx < 512; idx += 256) {
        int r = idx >> 4, c = (idx & 15)*8;
        *(uint4*)(sKV + r*KVS + c) =
            *(const uint4*)(g_kvh + (size_t)(bh*DIM + m0g + r)*DIM + c);
    }
    for (int i4 = tid; i4 < 4096; i4 += 256) {
        int e2 = i4 >> 5, ec = (i4 & 31)*4;
        float4 wv = w4[i4];
        *(uint32_t*)(sW + e2*KVS + ec)     = h2(wv.x, wv.y);
        *(uint32_t*)(sW + e2*KVS + ec + 2) = h2(wv.z, wv.w);
    }
    __syncthreads();

    int mt = warp & 1, ng = warp >> 1;
    int m0 = mt*16;
    float acc[4][4];
#pragma unroll
    for (int i = 0; i < 4; i++)
#pragma unroll
        for (int j = 0; j < 4; j++) acc[i][j] = 0.f;
    uint32_t aB = A_ADDR(sKV, m0, KVS);
#pragma unroll
    for (int kk = 0; kk < 8; kk++) {
        int k0 = kk*16;
        uint32_t a0,a1,a2,a3;
        ldsm4(a0,a1,a2,a3, aB + k0*2);
#pragma unroll
        for (int np = 0; np < 2; np++) {
            uint32_t b00,b01,b10,b11;
            ldsm4(b00,b01,b10,b11, B_ADDR(sW, ng*32 + np*16, KVS) + k0*2);
            mma16(acc[np*2],   a0,a1,a2,a3, b00,b01);
            mma16(acc[np*2+1], a0,a1,a2,a3, b10,b11);
        }
    }
    int g = lane >> 2, tig = lane & 3;
    __half* dst = g_mt + (size_t)bh*DIM*DIM;
    int row = m0g + m0 + g;
#pragma unroll
    for (int nt = 0; nt < 4; nt++) {
        int col = ng*32 + nt*8 + 2*tig;
        dst[col*DIM + row]         = __float2half_rn(acc[nt][0]);
        dst[(col+1)*DIM + row]     = __float2half_rn(acc[nt][1]);
        dst[col*DIM + row + 8]     = __float2half_rn(acc[nt][2]);
        dst[(col+1)*DIM + row + 8] = __float2half_rn(acc[nt][3]);
    }
}

// ============================================================
// K_fused: sparse attention + linear half, fp16 mma + ldmatrix
// grid = BHN*NB = 1024, 256 threads, 114432B smem -> 2 blocks/SM
// ============================================================
#define B0 8704
#define B1 18944
#define B2 29184
#define SPO 39424
#define PST2 264
#define STATS 56320
#define VSTR 72

__global__ void __launch_bounds__(256,2) k_fused(const float* __restrict__ bpr,
                                                 float* __restrict__ out) {
    extern __shared__ __half hsm[];
    __half* sQ = hsm;
    __half* sP = hsm + SPO;
    float* swmax = (float*)(hsm + STATS);
    float* swsum = swmax + 128;
    float* sks   = swsum + 128;
    float* sden  = sks + 128;

    int bid = blockIdx.x, bh = bid >> 5, qb = bid & 31;
    int tid = threadIdx.x, lane = tid & 31, warp = tid >> 5;
    int g = lane >> 2, tig = lane & 3;
    int mt = warp & 3, ns = warp >> 2;

    int lut[4];
#pragma unroll
    for (int t = 0; t < TOP; t++) lut[t] = g_lut[bid*TOP + t];
    if (tid < DIM) sks[tid] = g_ksum[bh*DIM + tid];

#define ISSUE64(SRC, DST) do {                                          \
        const __half* s_ = (SRC);                                       \
        _Pragma("unroll")                                               \
        for (int i_ = 0; i_ < 4; i_++) {                                \
            int idx_ = tid + 256*i_;                                    \
            int r_ = idx_ >> 4, c_ = (idx_ & 15)*8;                     \
            cpa16(s2u((DST) + r_*136 + c_), s_ + r_*128 + c_);          \
        }                                                               \
    } while (0)
#define ISSUE_VT(T, DST) do {                                           \
        const __half* s_ = g_vth + (size_t)bh*DIM*LSEQ + lut[T]*64;     \
        _Pragma("unroll")                                               \
        for (int i_ = 0; i_ < 4; i_++) {                                \
            int idx_ = tid + 256*i_;                                    \
            int r_ = idx_ >> 3, c_ = (idx_ & 7)*8;                      \
            cpa16(s2u((DST) + r_*VSTR + c_), s_ + (size_t)r_*LSEQ + c_);\
        }                                                               \
    } while (0)

    size_t qh_base = ((size_t)bh*LSEQ + (size_t)qb*BLK)*DIM;
    ISSUE64(g_qh + qh_base, sQ);
    ISSUE64(g_kh + ((size_t)bh*LSEQ + lut[0]*BLK)*DIM, hsm + B0);
    CP_COMMIT();                                                  // G1
    ISSUE64(g_kh + ((size_t)bh*LSEQ + lut[1]*BLK)*DIM, hsm + B1);
    CP_COMMIT();                                                  // G2
    ISSUE64(g_kh + ((size_t)bh*LSEQ + lut[2]*BLK)*DIM, hsm + B2);
    CP_COMMIT();                                                  // G3

    float accS[4][4][4];
#pragma unroll
    for (int t = 0; t < 4; t++)
#pragma unroll
        for (int i = 0; i < 4; i++)
#pragma unroll
            for (int j = 0; j < 4; j++) accS[t][i][j] = 0.f;

#define MMA_S(T, KB) do {                                               \
        uint32_t aB_ = A_ADDR(sQ, mt*16, 136);                          \
        uint32_t bB_ = B_ADDR((KB), ns*32, 136);                        \
        _Pragma("unroll")                                               \
        for (int kk = 0; kk < 8; kk++) {                                \
            int k0 = kk*16;                                             \
            uint32_t a0,a1,a2,a3, b00,b01,b10,b11;                      \
            ldsm4(a0,a1,a2,a3, aB_ + k0*2);                             \
            ldsm4(b00,b01,b10,b11, bB_ + k0*2);                         \
            mma16(accS[T][0], a0,a1,a2,a3, b00,b01);                    \
            mma16(accS[T][1], a0,a1,a2,a3, b10,b11);                    \
            ldsm4(b00,b01,b10,b11, bB_ + 16*136*2 + k0*2);              \
            mma16(accS[T][2], a0,a1,a2,a3, b00,b01);                    \
            mma16(accS[T][3], a0,a1,a2,a3, b10,b11);                    \
        }                                                               \
    } while (0)

    CP_WAIT(2); __syncthreads();
    MMA_S(0, hsm + B0); __syncthreads();
    ISSUE64(g_kh + ((size_t)bh*LSEQ + lut[3]*BLK)*DIM, hsm + B0); CP_COMMIT();  // G4
    CP_WAIT(2); __syncthreads();
    MMA_S(1, hsm + B1); __syncthreads();
    ISSUE_VT(0, hsm + B1); CP_COMMIT();                                          // G5
    CP_WAIT(2); __syncthreads();
    MMA_S(2, hsm + B2); __syncthreads();
    ISSUE_VT(1, hsm + B2); CP_COMMIT();                                          // G6
    CP_WAIT(2); __syncthreads();
    MMA_S(3, hsm + B0); __syncthreads();
    ISSUE_VT(2, hsm + B0); CP_COMMIT();                                          // G7

    // ---- softmax over registers with cross-warp stats ----
    const float scale = 0.08838834764831845f;
    int row0 = mt*16 + g, row1 = row0 + 8;
    {
        float m0v = -FLT_MAX, m1v = -FLT_MAX;
#pragma unroll
        for (int t = 0; t < 4; t++)
#pragma unroll
            for (int nt = 0; nt < 4; nt++) {
                m0v = fmaxf(m0v, fmaxf(accS[t][nt][0], accS[t][nt][1]));
                m1v = fmaxf(m1v, fmaxf(accS[t][nt][2], accS[t][nt][3]));
            }
        m0v = fmaxf(m0v, __shfl_xor_sync(0xffffffffu, m0v, 1));
        m0v = fmaxf(m0v, __shfl_xor_sync(0xffffffffu, m0v, 2));
        m1v = fmaxf(m1v, __shfl_xor_sync(0xffffffffu, m1v, 1));
        m1v = fmaxf(m1v, __shfl_xor_sync(0xffffffffu, m1v, 2));
        if (tig == 0) { swmax[row0*2+ns] = m0v; swmax[row1*2+ns] = m1v; }
    }
    __syncthreads();
    {
        float gm0 = fmaxf(swmax[row0*2], swmax[row0*2+1]);
        float gm1 = fmaxf(swmax[row1*2], swmax[row1*2+1]);
        float s0 = 0.f, s1 = 0.f;
#pragma unroll
        for (int t = 0; t < 4; t++)
#pragma unroll
            for (int nt = 0; nt < 4; nt++) {
                float e0 = __expf((accS[t][nt][0]-gm0)*scale);
                float e1 = __expf((accS[t][nt][1]-gm0)*scale);
                float e2 = __expf((accS[t][nt][2]-gm1)*scale);
                float e3 = __expf((accS[t][nt][3]-gm1)*scale);
                s0 += e0 + e1; s1 += e2 + e3;
                int col = t*64 + ns*32 + nt*8 + 2*tig;
                *(uint32_t*)(sP + row0*PST2 + col) = h2(e0, e1);
                *(uint32_t*)(sP + row1*PST2 + col) = h2(e2, e3);
            }
        s0 += __shfl_xor_sync(0xffffffffu, s0, 1);
        s0 += __shfl_xor_sync(0xffffffffu, s0, 2);
        s1 += __shfl_xor_sync(0xffffffffu, s1, 1);
        s1 += __shfl_xor_sync(0xffffffffu, s1, 2);
        if (tig == 0) { swsum[row0*2+ns] = s0; swsum[row1*2+ns] = s1; }
    }

    // ---- PV ----
    float oac[8][4];
#pragma unroll
    for (int i = 0; i < 8; i++)
#pragma unroll
        for (int j = 0; j < 4; j++) oac[i][j] = 0.f;

#define MMA_PV(T, VB) do {                                              \
        uint32_t aB_ = A_ADDR(sP, mt*16, PST2) + (T)*64*2;              \
        _Pragma("unroll")                                               \
        for (int kk = 0; kk < 4; kk++) {                                \
            int k0 = kk*16;                                             \
            uint32_t a0,a1,a2,a3;                                       \
            ldsm4(a0,a1,a2,a3, aB_ + k0*2);                             \
            _Pragma("unroll")                                           \
            for (int np = 0; np < 4; np++) {                            \
                uint32_t b00,b01,b10,b11;                               \
                ldsm4(b00,b01,b10,b11, B_ADDR((VB), ns*64+np*16, VSTR) + k0*2); \
                mma16(oac[np*2],   a0,a1,a2,a3, b00,b01);               \
                mma16(oac[np*2+1], a0,a1,a2,a3, b10,b11);               \
            }                                                           \
        }                                                               \
    } while (0)

    CP_WAIT(2); __syncthreads();            // V0 ready
    MMA_PV(0, hsm + B1); __syncthreads();
    ISSUE_VT(3, hsm + B1); CP_COMMIT();                                          // G8
    CP_WAIT(2); __syncthreads();            // V1 ready
    MMA_PV(1, hsm + B2);
    __syncthreads();
    ISSUE64(g_phiqh + qh_base, hsm + B2); CP_COMMIT();                           // G9
    CP_WAIT(2); __syncthreads();            // V2 ready (G7)
    MMA_PV(2, hsm + B0);
    __syncthreads();                        // base/sQ + B0 dead across all warps
    {
        const __half* s_ = g_mt + (size_t)bh*DIM*DIM;
#pragma unroll
        for (int i_ = 0; i_ < 8; i_++) {
            int idx_ = tid + 256*i_;
            int r_ = idx_ >> 4, c_ = (idx_ & 15)*8;
            cpa16(s2u(hsm + r_*136 + c_), s_ + r_*128 + c_);
        }
        CP_COMMIT();                                                             // G10
    }
    CP_WAIT(2); __syncthreads();            // V3 ready (G8)
    MMA_PV(3, hsm + B1);

    // ---- den = phi_q . ksum ----
    CP_WAIT(1); __syncthreads();            // phi_q ready (G9)
    for (int r = warp; r < BLK; r += 8) {
        const __half* pr = hsm + B2 + r*136;
        float dp = __half2float(pr[lane])    * sks[lane]
                 + __half2float(pr[lane+32]) * sks[lane+32]
                 + __half2float(pr[lane+64]) * sks[lane+64]
                 + __half2float(pr[lane+96]) * sks[lane+96];
#pragma unroll
        for (int o = 16; o; o >>= 1) dp += __shfl_xor_sync(0xffffffffu, dp, o);
        if (lane == 0) sden[r] = 1.f/(1e-5f + dp);
    }
    CP_WAIT(0);                             // Mt ready (G10)
    __syncthreads();

    // ---- linear GEMM: o_pre = phi_q @ M ----
    float acc2[8][4];
#pragma unroll
    for (int i = 0; i < 8; i++)
#pragma unroll
        for (int j = 0; j < 4; j++) acc2[i][j] = 0.f;
    {
        uint32_t aB_ = A_ADDR(hsm + B2, mt*16, 136);
#pragma unroll
        for (int kk = 0; kk < 8; kk++) {
            int k0 = kk*16;
            uint32_t a0,a1,a2,a3;
            ldsm4(a0,a1,a2,a3, aB_ + k0*2);
#pragma unroll
            for (int np = 0; np < 4; np++) {
                uint32_t b00,b01,b10,b11;
                ldsm4(b00,b01,b10,b11, B_ADDR(hsm, ns*64+np*16, 136) + k0*2);
                mma16(acc2[np*2],   a0,a1,a2,a3, b00,b01);
                mma16(acc2[np*2+1], a0,a1,a2,a3, b10,b11);
            }
        }
    }

    // ---- epilogue: out = o_s + o_l + bias ----
    float inv0 = 1.f/(swsum[row0*2] + swsum[row0*2+1]);
    float inv1 = 1.f/(swsum[row1*2] + swsum[row1*2+1]);
    float dn0 = sden[row0], dn1 = sden[row1];
    size_t obase = ((size_t)bh*LSEQ + (size_t)qb*BLK)*DIM;
#pragma unroll
    for (int nt = 0; nt < 8; nt++) {
        int col = ns*64 + nt*8 + 2*tig;
        float bb0 = bpr[col], bb1 = bpr[col+1];
        float* op0 = out + obase + (size_t)row0*DIM + col;
        float* op1 = out + obase + (size_t)row1*DIM + col;
        *(float2*)op0 = make_float2(oac[nt][0]*inv0 + acc2[nt][0]*dn0 + bb0,
                                    oac[nt][1]*inv0 + acc2[nt][1]*dn0 + bb1);
        *(float2*)op1 = make_float2(oac[nt][2]*inv1 + acc2[nt][2]*dn1 + bb0,
                                    oac[nt][3]*inv1 + acc2[nt][3]*dn1 + bb1);
    }
}

// ============================================================
extern "C" void kernel_launch(void* const* d_in, const int* in_sizes, int n_in,
                              void* d_out, int out_size) {
    const float* q = (const float*)d_in[0];
    const float* k = (const float*)d_in[1];
    const float* v = (const float*)d_in[2];
    const float* w = (const float*)d_in[3];
    const float* b = (const float*)d_in[4];
    float* out = (float*)d_out;

    int smKV = 2*128*KVS*2;                       // 69632
    int smKW = (32*KVS + 128*KVS)*2;              // 43520
    int smF  = STATS*2 + 448*4;                   // 114432
    cudaFuncSetAttribute(k_kvsum, cudaFuncAttributeMaxDynamicSharedMemorySize, smKV);
    cudaFuncSetAttribute(k_kvw,   cudaFuncAttributeMaxDynamicSharedMemorySize, smKW);
    cudaFuncSetAttribute(k_fused, cudaFuncAttributeMaxDynamicSharedMemorySize, smF);

    k_prep<<<BHN*NB, 256>>>((const float4*)q, (const float4*)k, (const float4*)v);
    k_topk<<<BHN, 1024>>>();
    k_kvsum<<<NCH*BHN, 256, smKV>>>();
    k_red<<<(BHN*DIM*DIM)/256, 256>>>();
    k_kvw<<<BHN*4, 256, smKW>>>((const float4*)w);
    k_fused<<<BHN*NB, 256, smF>>>(b, out);
}